// round 2
// baseline (speedup 1.0000x reference)
#include <cuda_runtime.h>
#include <math.h>

// ---------------- problem constants ----------------
#define T     2048
#define HD    2048          // hidden
#define E     8             // routed experts
#define IM    1408          // moe intermediate
#define ISH   2816          // shared intermediate
// GEMM tile config
#define BM    128
#define BN    64
#define BK    16
#define MAXP  (2*T + E*BM)  // padded pair rows (offsets aligned to BM)
#define NTILES (MAXP/BM)    // 40

// ---------------- device scratch (static; no allocs) ----------------
__device__ int   d_topk_idx[2*T];
__device__ float d_topk_w[2*T];
__device__ int   d_cnt[E];
__device__ int   d_off[E];
__device__ int   d_npad;
__device__ int   d_tile_e[NTILES];
__device__ int   d_ptok[MAXP];       // padded pair row -> token
__device__ int   d_pslot[2*T];       // (token, j) -> padded pair row
__device__ float d_gbuf[(size_t)MAXP*IM];
__device__ float d_ubuf[(size_t)MAXP*IM];
__device__ float d_hbuf[(size_t)MAXP*IM];
__device__ float d_yp  [(size_t)MAXP*HD];
__device__ float d_sg  [(size_t)T*ISH];
__device__ float d_su  [(size_t)T*ISH];
__device__ float d_sh  [(size_t)T*ISH];

// ---------------- router: sigmoid scores + group-limited top-2 ----------------
__global__ void router_k(const float* __restrict__ x,
                         const float* __restrict__ rw,
                         const float* __restrict__ bias)
{
    __shared__ float xs[HD];
    __shared__ float logits[E];
    int t   = blockIdx.x;
    int tid = threadIdx.x;
    for (int i = tid; i < HD; i += blockDim.x) xs[i] = x[(size_t)t*HD + i];
    __syncthreads();
    int wid = tid >> 5, lane = tid & 31;
    if (wid < E) {
        float s = 0.f;
        for (int k = lane; k < HD; k += 32) s += xs[k] * rw[wid*HD + k];
        #pragma unroll
        for (int o = 16; o; o >>= 1) s += __shfl_down_sync(0xffffffffu, s, o);
        if (!lane) logits[wid] = s;
    }
    __syncthreads();
    if (tid == 0) {
        float sc[E], sfc[E];
        #pragma unroll
        for (int e = 0; e < E; e++) {
            sc[e]  = 1.f / (1.f + expf(-logits[e]));
            sfc[e] = sc[e] + bias[e];
        }
        // group scores: 4 groups of 2 -> top-2 of 2 == sum of both
        float gs[4];
        #pragma unroll
        for (int g = 0; g < 4; g++) gs[g] = sfc[2*g] + sfc[2*g+1];
        int g1 = 0;
        #pragma unroll
        for (int g = 1; g < 4; g++) if (gs[g] > gs[g1]) g1 = g;
        int g2 = -1;
        #pragma unroll
        for (int g = 0; g < 4; g++) { if (g == g1) continue; if (g2 < 0 || gs[g] > gs[g2]) g2 = g; }
        float masked[E];
        #pragma unroll
        for (int e = 0; e < E; e++) { int g = e >> 1; masked[e] = (g == g1 || g == g2) ? sfc[e] : 0.f; }
        int i1 = 0;
        #pragma unroll
        for (int e = 1; e < E; e++) if (masked[e] > masked[i1]) i1 = e;
        int i2 = -1;
        #pragma unroll
        for (int e = 0; e < E; e++) { if (e == i1) continue; if (i2 < 0 || masked[e] > masked[i2]) i2 = e; }
        float w1 = sc[i1], w2 = sc[i2];
        float inv = 2.5f / (w1 + w2 + 1e-20f);
        d_topk_idx[2*t]   = i1;  d_topk_idx[2*t+1] = i2;
        d_topk_w[2*t]     = w1 * inv;
        d_topk_w[2*t+1]   = w2 * inv;
    }
}

// ---------------- deterministic pair-list build (1 block) ----------------
__global__ void build_pairs_k()
{
    __shared__ int cnts[E], offs[E];
    int tid = threadIdx.x, wid = tid >> 5, lane = tid & 31;
    if (wid < E) {
        int c = 0;
        for (int base = 0; base < T; base += 32) {
            int t = base + lane;
            bool sel = (d_topk_idx[2*t] == wid) || (d_topk_idx[2*t+1] == wid);
            c += __popc(__ballot_sync(0xffffffffu, sel));
        }
        if (!lane) cnts[wid] = c;
    }
    __syncthreads();
    if (tid == 0) {
        int o = 0;
        for (int e = 0; e < E; e++) {
            offs[e] = o; d_off[e] = o; d_cnt[e] = cnts[e];
            int nt = (cnts[e] + BM - 1) / BM;
            o += nt * BM;
        }
        d_npad = o;
        int tcur = 0;
        for (int e = 0; e < E; e++) {
            int t0 = offs[e] / BM, nt = (cnts[e] + BM - 1) / BM;
            for (int i = 0; i < nt; i++) d_tile_e[t0 + i] = e;
            tcur = t0 + nt;
        }
        for (int i = tcur; i < NTILES; i++) d_tile_e[i] = -1;
    }
    __syncthreads();
    if (wid < E) {
        int pos = offs[wid];
        for (int base = 0; base < T; base += 32) {
            int t = base + lane;
            int e0 = d_topk_idx[2*t], e1 = d_topk_idx[2*t+1];
            int j = (e0 == wid) ? 0 : ((e1 == wid) ? 1 : -1);
            unsigned m = __ballot_sync(0xffffffffu, j >= 0);
            if (j >= 0) {
                int p = pos + __popc(m & ((1u << lane) - 1u));
                d_ptok[p]      = t;
                d_pslot[2*t+j] = p;
            }
            pos += __popc(m);
        }
    }
}

// ---------------- generic tiled fp32 GEMM:  C[m,n] = sum_k A[row(m),k] * B[n,k] ----------------
// MODE 0: routed gate/up  (A=x gathered via ptok; B=(gate|up)_w[e]; C=(gbuf|ubuf); N=IM, K=HD)
// MODE 1: routed down     (A=hbuf pair rows;     B=down_w[e];       C=yp;         N=HD, K=IM)
// MODE 2: shared gate/up  (A=x;                  B=(sgw|suw);       C=(sg|su);    N=ISH,K=HD)
// MODE 3: shared down     (A=sh;                 B=sdw;             C=out;        N=HD, K=ISH)
template<int MODE>
__global__ void __launch_bounds__(256)
gemm_k(const float* __restrict__ A,
       const float* __restrict__ Bg, const float* __restrict__ Bu,
       float* __restrict__ Cg, float* __restrict__ Cu)
{
    constexpr int N   = (MODE==0) ? IM : (MODE==1) ? HD : (MODE==2) ? ISH : HD;
    constexpr int K   = (MODE==0) ? HD : (MODE==1) ? IM : (MODE==2) ? HD  : ISH;
    constexpr int LDA = (MODE==0) ? HD : (MODE==1) ? IM : (MODE==2) ? HD  : ISH;

    const int m0 = blockIdx.x * BM;
    const int n0 = blockIdx.y * BN;

    int row_limit;
    const float* __restrict__ Bp;
    float* __restrict__ Cp;
    if (MODE <= 1) {
        int e = d_tile_e[blockIdx.x];
        if (e < 0) return;
        row_limit = d_off[e] + d_cnt[e];
        if (m0 >= row_limit) return;
        if (MODE == 0) {
            Bp = (blockIdx.z ? Bu : Bg) + (size_t)e * IM * HD;
            Cp = blockIdx.z ? Cu : Cg;
        } else {
            Bp = Bg + (size_t)e * HD * IM;
            Cp = Cg;
        }
    } else {
        row_limit = T;
        if (MODE == 2) { Bp = blockIdx.z ? Bu : Bg; Cp = blockIdx.z ? Cu : Cg; }
        else           { Bp = Bg; Cp = Cg; }
    }

    __shared__ __align__(16) float As[BK][BM + 4];
    __shared__ __align__(16) float Bs[BK][BN + 4];

    const int tid = threadIdx.x;
    const int tx  = tid & 15;       // 0..15 -> 4 cols each
    const int ty  = tid >> 4;       // 0..15 -> 8 rows each
    const int lr  = tid >> 4;       // load row base
    const int lk  = tid & 15;       // load k

    // precompute gathered A-row indices + validity
    int  arow[8];
    bool aok[8];
    #pragma unroll
    for (int i = 0; i < 8; i++) {
        int r = m0 + lr + 16*i;
        aok[i]  = (r < row_limit);
        int src = r;
        if (MODE == 0) src = aok[i] ? d_ptok[r] : 0;
        arow[i] = src;
    }

    float acc[8][4] = {};

    for (int k0 = 0; k0 < K; k0 += BK) {
        #pragma unroll
        for (int i = 0; i < 8; i++) {
            float v = aok[i] ? __ldg(&A[(size_t)arow[i]*LDA + k0 + lk]) : 0.f;
            As[lk][lr + 16*i] = v;
        }
        #pragma unroll
        for (int i = 0; i < 4; i++) {
            int n = lr + 16*i;
            Bs[lk][n] = __ldg(&Bp[(size_t)(n0 + n)*K + k0 + lk]);
        }
        __syncthreads();
        #pragma unroll
        for (int kk = 0; kk < BK; kk++) {
            float4 a0 = *(const float4*)&As[kk][ty*8];
            float4 a1 = *(const float4*)&As[kk][ty*8 + 4];
            float4 bv = *(const float4*)&Bs[kk][tx*4];
            float a[8] = {a0.x, a0.y, a0.z, a0.w, a1.x, a1.y, a1.z, a1.w};
            float b[4] = {bv.x, bv.y, bv.z, bv.w};
            #pragma unroll
            for (int i = 0; i < 8; i++)
                #pragma unroll
                for (int j = 0; j < 4; j++)
                    acc[i][j] = fmaf(a[i], b[j], acc[i][j]);
        }
        __syncthreads();
    }

    #pragma unroll
    for (int i = 0; i < 8; i++) {
        int r = m0 + ty*8 + i;
        if (r < row_limit) {
            float4 v = make_float4(acc[i][0], acc[i][1], acc[i][2], acc[i][3]);
            *(float4*)&Cp[(size_t)r*N + n0 + tx*4] = v;
        }
    }
}

// ---------------- swiglu elementwise: h = silu(g) * u ----------------
__global__ void swiglu_k(const float* __restrict__ g, const float* __restrict__ u,
                         float* __restrict__ h, int nrows, int ld)
{
    int rows = (nrows < 0) ? d_npad : nrows;
    size_t n = (size_t)rows * ld;
    size_t stride = (size_t)gridDim.x * blockDim.x;
    for (size_t i = (size_t)blockIdx.x*blockDim.x + threadIdx.x; i < n; i += stride) {
        float gv = g[i];
        h[i] = (gv / (1.f + expf(-gv))) * u[i];
    }
}

// ---------------- combine: out += w0*yp[p0] + w1*yp[p1] ----------------
__global__ void combine_k(float* __restrict__ out)
{
    size_t n = (size_t)T * HD;
    size_t stride = (size_t)gridDim.x * blockDim.x;
    for (size_t i = (size_t)blockIdx.x*blockDim.x + threadIdx.x; i < n; i += stride) {
        int t   = (int)(i >> 11);       // HD = 2048
        int col = (int)(i & 2047);
        int   p0 = d_pslot[2*t],   p1 = d_pslot[2*t+1];
        float w0 = d_topk_w[2*t],  w1 = d_topk_w[2*t+1];
        out[i] += w0 * d_yp[(size_t)p0*HD + col] + w1 * d_yp[(size_t)p1*HD + col];
    }
}

// ---------------- launch ----------------
extern "C" void kernel_launch(void* const* d_in, const int* in_sizes, int n_in,
                              void* d_out, int out_size)
{
    const float* x    = (const float*)d_in[0];
    const float* rw   = (const float*)d_in[1];
    const float* bias = (const float*)d_in[2];
    const float* gw   = (const float*)d_in[3];
    const float* uw   = (const float*)d_in[4];
    const float* dw   = (const float*)d_in[5];
    const float* sgw  = (const float*)d_in[6];
    const float* suw  = (const float*)d_in[7];
    const float* sdw  = (const float*)d_in[8];
    float* out = (float*)d_out;

    float *gbuf, *ubuf, *hbuf, *yp, *sg, *su, *sh;
    cudaGetSymbolAddress((void**)&gbuf, d_gbuf);
    cudaGetSymbolAddress((void**)&ubuf, d_ubuf);
    cudaGetSymbolAddress((void**)&hbuf, d_hbuf);
    cudaGetSymbolAddress((void**)&yp,   d_yp);
    cudaGetSymbolAddress((void**)&sg,   d_sg);
    cudaGetSymbolAddress((void**)&su,   d_su);
    cudaGetSymbolAddress((void**)&sh,   d_sh);

    router_k<<<T, 256>>>(x, rw, bias);
    build_pairs_k<<<1, 256>>>();

    // routed gate+up: z=0 gate, z=1 up
    gemm_k<0><<<dim3(NTILES, IM/BN, 2), 256>>>(x, gw, uw, gbuf, ubuf);
    swiglu_k<<<2048, 256>>>(gbuf, ubuf, hbuf, -1, IM);
    // routed down -> per-pair outputs
    gemm_k<1><<<dim3(NTILES, HD/BN, 1), 256>>>(hbuf, dw, nullptr, yp, nullptr);

    // shared expert
    gemm_k<2><<<dim3(T/BM, ISH/BN, 2), 256>>>(x, sgw, suw, sg, su);
    swiglu_k<<<2048, 256>>>(sg, su, sh, T, ISH);
    gemm_k<3><<<dim3(T/BM, HD/BN, 1), 256>>>(sh, sdw, nullptr, out, nullptr);

    // out += routed contributions
    combine_k<<<2048, 256>>>(out);
}

// round 7
// speedup vs baseline: 2.2759x; 2.2759x over previous
#include <cuda_runtime.h>
#include <cuda_bf16.h>
#include <cstdint>
#include <math.h>

// ---------------- problem constants ----------------
#define T     2048
#define HD    2048          // hidden
#define E     8             // routed experts
#define IM    1408          // moe intermediate
#define ISH   2816          // shared intermediate
#define BM    128
#define BK    64            // bf16 k elems per stage (=128B rows)
#define MAXP  (2*T + E*BM)  // 5120 padded pair rows
#define NTILES (MAXP/BM)    // 40

// gu stage smem layout (bytes)
#define GU_AH 0
#define GU_AL 16384
#define GU_GH 32768
#define GU_GL 40960
#define GU_UH 49152
#define GU_UL 57344
#define GU_STAGE 65536
// down stage layout
#define DN_AH 0
#define DN_AL 16384
#define DN_BH 32768
#define DN_BL 49152
#define DN_STAGE 65536
#define SMEM_BYTES (2*GU_STAGE)   // 131072 for both kernels

#define SMEM_SWIZZLE_128B(off) ((off) ^ (((off) >> 3) & 0x70))

__device__ __forceinline__ uint32_t smem_to_u32(const void* p) {
    uint32_t a;
    asm("{ .reg .u64 t; cvta.to.shared.u64 t, %1; cvt.u32.u64 %0, t; }" : "=r"(a) : "l"(p));
    return a;
}

#define LDSM_X4(d0,d1,d2,d3,a) \
    asm volatile("ldmatrix.sync.aligned.m8n8.x4.shared.b16 {%0,%1,%2,%3}, [%4];" \
        : "=r"(d0), "=r"(d1), "=r"(d2), "=r"(d3) : "r"(a))

#define MMA16816(d, a, b0, b1) \
    asm volatile("mma.sync.aligned.m16n8k16.row.col.f32.bf16.bf16.f32 " \
        "{%0,%1,%2,%3}, {%4,%5,%6,%7}, {%8,%9}, {%0,%1,%2,%3};" \
        : "+f"((d)[0]), "+f"((d)[1]), "+f"((d)[2]), "+f"((d)[3]) \
        : "r"((a)[0]), "r"((a)[1]), "r"((a)[2]), "r"((a)[3]), "r"(b0), "r"(b1))

// fp32 -> bf16 hi/lo split of two consecutive values, packed bf16x2
__device__ __forceinline__ uint32_t pack2(float x, float y, uint32_t& lob) {
    __nv_bfloat162 h = __float22bfloat162_rn(make_float2(x, y));
    float2 hf = __bfloat1622float2(h);
    __nv_bfloat162 l = __float22bfloat162_rn(make_float2(x - hf.x, y - hf.y));
    lob = *reinterpret_cast<uint32_t*>(&l);
    return *reinterpret_cast<uint32_t*>(&h);
}

// ---------------- device scratch (static) ----------------
__device__ int   d_topk_idx[2*T];
__device__ float d_topk_w[2*T];
__device__ int   d_cnt[E];
__device__ int   d_off[E];
__device__ int   d_tile_e[NTILES];
__device__ int   d_ptok[MAXP];
__device__ int   d_pslot[2*T];
// pre-split bf16 hi/lo planes
__device__ __nv_bfloat16 w_g_h[(size_t)E*IM*HD],  w_g_l[(size_t)E*IM*HD];
__device__ __nv_bfloat16 w_u_h[(size_t)E*IM*HD],  w_u_l[(size_t)E*IM*HD];
__device__ __nv_bfloat16 w_d_h[(size_t)E*HD*IM],  w_d_l[(size_t)E*HD*IM];
__device__ __nv_bfloat16 w_sg_h[(size_t)ISH*HD],  w_sg_l[(size_t)ISH*HD];
__device__ __nv_bfloat16 w_su_h[(size_t)ISH*HD],  w_su_l[(size_t)ISH*HD];
__device__ __nv_bfloat16 w_sd_h[(size_t)HD*ISH],  w_sd_l[(size_t)HD*ISH];
__device__ __nv_bfloat16 x_hi[(size_t)T*HD],      x_lo[(size_t)T*HD];
__device__ __nv_bfloat16 h_hi[(size_t)MAXP*IM],   h_lo[(size_t)MAXP*IM];
__device__ __nv_bfloat16 sh_hi[(size_t)T*ISH],    sh_lo[(size_t)T*ISH];
__device__ float d_yp[(size_t)MAXP*HD];

// ---------------- split: fp32 -> bf16 hi + lo ----------------
__global__ void split_k(const float* __restrict__ s,
                        __nv_bfloat16* __restrict__ hi, __nv_bfloat16* __restrict__ lo,
                        size_t n4)
{
    size_t stride = (size_t)gridDim.x * blockDim.x;
    const float4* s4 = (const float4*)s;
    uint2* h2 = (uint2*)hi;
    uint2* l2 = (uint2*)lo;
    for (size_t i = (size_t)blockIdx.x * blockDim.x + threadIdx.x; i < n4; i += stride) {
        float4 v = s4[i];
        uint32_t l0, l1;
        uint32_t h0 = pack2(v.x, v.y, l0);
        uint32_t h1 = pack2(v.z, v.w, l1);
        h2[i] = make_uint2(h0, h1);
        l2[i] = make_uint2(l0, l1);
    }
}

// ---------------- router ----------------
__global__ void router_k(const float* __restrict__ x,
                         const float* __restrict__ rw,
                         const float* __restrict__ bias)
{
    __shared__ float xs[HD];
    __shared__ float logits[E];
    int t = blockIdx.x, tid = threadIdx.x;
    for (int i = tid; i < HD; i += blockDim.x) xs[i] = x[(size_t)t*HD + i];
    __syncthreads();
    int wid = tid >> 5, lane = tid & 31;
    if (wid < E) {
        float s = 0.f;
        for (int k = lane; k < HD; k += 32) s += xs[k] * rw[wid*HD + k];
        #pragma unroll
        for (int o = 16; o; o >>= 1) s += __shfl_down_sync(0xffffffffu, s, o);
        if (!lane) logits[wid] = s;
    }
    __syncthreads();
    if (tid == 0) {
        float sc[E], sfc[E];
        #pragma unroll
        for (int e = 0; e < E; e++) {
            sc[e]  = 1.f / (1.f + expf(-logits[e]));
            sfc[e] = sc[e] + bias[e];
        }
        float gs[4];
        #pragma unroll
        for (int g = 0; g < 4; g++) gs[g] = sfc[2*g] + sfc[2*g+1];
        int g1 = 0;
        #pragma unroll
        for (int g = 1; g < 4; g++) if (gs[g] > gs[g1]) g1 = g;
        int g2 = -1;
        #pragma unroll
        for (int g = 0; g < 4; g++) { if (g == g1) continue; if (g2 < 0 || gs[g] > gs[g2]) g2 = g; }
        float masked[E];
        #pragma unroll
        for (int e = 0; e < E; e++) { int g = e >> 1; masked[e] = (g == g1 || g == g2) ? sfc[e] : 0.f; }
        int i1 = 0;
        #pragma unroll
        for (int e = 1; e < E; e++) if (masked[e] > masked[i1]) i1 = e;
        int i2 = -1;
        #pragma unroll
        for (int e = 0; e < E; e++) { if (e == i1) continue; if (i2 < 0 || masked[e] > masked[i2]) i2 = e; }
        float w1 = sc[i1], w2 = sc[i2];
        float inv = 2.5f / (w1 + w2 + 1e-20f);
        d_topk_idx[2*t] = i1; d_topk_idx[2*t+1] = i2;
        d_topk_w[2*t]   = w1 * inv;
        d_topk_w[2*t+1] = w2 * inv;
    }
}

// ---------------- deterministic pair list ----------------
__global__ void build_pairs_k()
{
    __shared__ int cnts[E], offs[E];
    int tid = threadIdx.x, wid = tid >> 5, lane = tid & 31;
    for (int i = tid; i < MAXP; i += blockDim.x) d_ptok[i] = 0;  // padded rows -> token 0
    if (wid < E) {
        int c = 0;
        for (int base = 0; base < T; base += 32) {
            int t = base + lane;
            bool sel = (d_topk_idx[2*t] == wid) || (d_topk_idx[2*t+1] == wid);
            c += __popc(__ballot_sync(0xffffffffu, sel));
        }
        if (!lane) cnts[wid] = c;
    }
    __syncthreads();
    if (tid == 0) {
        int o = 0;
        for (int e = 0; e < E; e++) {
            offs[e] = o; d_off[e] = o; d_cnt[e] = cnts[e];
            o += ((cnts[e] + BM - 1) / BM) * BM;
        }
        int tcur = 0;
        for (int e = 0; e < E; e++) {
            int t0 = offs[e] / BM, nt = (cnts[e] + BM - 1) / BM;
            for (int i = 0; i < nt; i++) d_tile_e[t0 + i] = e;
            tcur = t0 + nt;
        }
        for (int i = tcur; i < NTILES; i++) d_tile_e[i] = -1;
    }
    __syncthreads();
    if (wid < E) {
        int pos = offs[wid];
        for (int base = 0; base < T; base += 32) {
            int t = base + lane;
            int e0 = d_topk_idx[2*t], e1 = d_topk_idx[2*t+1];
            int j = (e0 == wid) ? 0 : ((e1 == wid) ? 1 : -1);
            unsigned m = __ballot_sync(0xffffffffu, j >= 0);
            if (j >= 0) {
                int p = pos + __popc(m & ((1u << lane) - 1u));
                d_ptok[p] = t;
                d_pslot[2*t+j] = p;
            }
            pos += __popc(m);
        }
    }
}

// ============ fused gate+up GEMM (mma.sync bf16 3-pass) + SwiGLU epilogue ============
// CTA 128x64, warp tile 32x32 per output plane. K = HD.
template<int ROUTED>
__global__ void __launch_bounds__(256)
gu_k(const __nv_bfloat16* __restrict__ Xh, const __nv_bfloat16* __restrict__ Xl,
     const __nv_bfloat16* __restrict__ Gh0, const __nv_bfloat16* __restrict__ Gl0,
     const __nv_bfloat16* __restrict__ Uh0, const __nv_bfloat16* __restrict__ Ul0,
     __nv_bfloat16* __restrict__ Chi, __nv_bfloat16* __restrict__ Clo)
{
    constexpr int NS  = HD / BK;            // 32
    constexpr int CLD = ROUTED ? IM : ISH;
    extern __shared__ char smem[];
    const uint32_t sb = smem_to_u32(smem);
    const int tid = threadIdx.x, wid = tid >> 5, lane = tid & 31;
    const int m0 = blockIdx.x * BM, n0 = blockIdx.y * 64;

    const __nv_bfloat16 *gh = Gh0, *gl = Gl0, *uh = Uh0, *ul = Ul0;
    if (ROUTED) {
        int e = d_tile_e[blockIdx.x];
        if (e < 0) return;
        size_t eo = (size_t)e * IM * HD;
        gh += eo; gl += eo; uh += eo; ul += eo;
    }

    // copy descriptors: rb = row base, ch = 16B chunk within 128B row
    const int rb  = tid >> 3;               // 0..31
    const int chB = (tid & 7) * 16;         // byte offset of chunk
    const int chE = (tid & 7) * 8;          // element offset
    int srowA[4];
    #pragma unroll
    for (int i = 0; i < 4; i++) {
        int gr = m0 + rb + i * 32;
        srowA[i] = ROUTED ? d_ptok[gr] : gr;
    }

    auto copy = [&](int s, int buf) {
        char* bb = smem + (size_t)buf * GU_STAGE;
        const size_t ke = (size_t)s * BK + chE;
        #pragma unroll
        for (int i = 0; i < 4; i++) {
            int r = rb + i * 32;
            uint32_t sw = SMEM_SWIZZLE_128B((uint32_t)(r * 128 + chB));
            *(uint4*)(bb + GU_AH + sw) = *(const uint4*)(Xh + (size_t)srowA[i] * HD + ke);
            *(uint4*)(bb + GU_AL + sw) = *(const uint4*)(Xl + (size_t)srowA[i] * HD + ke);
        }
        #pragma unroll
        for (int i = 0; i < 2; i++) {
            int r = (rb & 31) + i * 32;     // 0..63
            uint32_t sw = SMEM_SWIZZLE_128B((uint32_t)(r * 128 + chB));
            size_t go = (size_t)(n0 + r) * HD + ke;
            *(uint4*)(bb + GU_GH + sw) = *(const uint4*)(gh + go);
            *(uint4*)(bb + GU_GL + sw) = *(const uint4*)(gl + go);
            *(uint4*)(bb + GU_UH + sw) = *(const uint4*)(uh + go);
            *(uint4*)(bb + GU_UL + sw) = *(const uint4*)(ul + go);
        }
    };

    // warp mapping: 4(m) x 2(n)
    const int mw = (wid & 3) * 32, nw = (wid >> 2) * 32;
    const int arow = mw + (lane & 15);
    const int acs  = lane >> 4;                                  // 0/1
    const int brow = nw + (lane & 7) + ((lane & 16) ? 8 : 0);
    const int bcs  = (lane >> 3) & 1;

    float accg[2][4][4] = {}, accu[2][4][4] = {};

    copy(0, 0);
    __syncthreads();
    for (int s = 0; s < NS; s++) {
        const int b = s & 1;
        if (s + 1 < NS) copy(s + 1, b ^ 1);
        const uint32_t base = sb + b * GU_STAGE;
        #pragma unroll
        for (int k = 0; k < 4; k++) {
            uint32_t ah[2][4], al[2][4];
            #pragma unroll
            for (int mt = 0; mt < 2; mt++) {
                uint32_t off = SMEM_SWIZZLE_128B((uint32_t)((arow + mt*16) * 128 + (2*k + acs) * 16));
                LDSM_X4(ah[mt][0], ah[mt][1], ah[mt][2], ah[mt][3], base + GU_AH + off);
                LDSM_X4(al[mt][0], al[mt][1], al[mt][2], al[mt][3], base + GU_AL + off);
            }
            uint32_t bo0 = SMEM_SWIZZLE_128B((uint32_t)(brow        * 128 + (2*k + bcs) * 16));
            uint32_t bo1 = SMEM_SWIZZLE_128B((uint32_t)((brow + 16) * 128 + (2*k + bcs) * 16));
            uint32_t gbh[8], gbl[8], ubh[8], ubl[8];
            LDSM_X4(gbh[0], gbh[1], gbh[2], gbh[3], base + GU_GH + bo0);
            LDSM_X4(gbh[4], gbh[5], gbh[6], gbh[7], base + GU_GH + bo1);
            LDSM_X4(gbl[0], gbl[1], gbl[2], gbl[3], base + GU_GL + bo0);
            LDSM_X4(gbl[4], gbl[5], gbl[6], gbl[7], base + GU_GL + bo1);
            LDSM_X4(ubh[0], ubh[1], ubh[2], ubh[3], base + GU_UH + bo0);
            LDSM_X4(ubh[4], ubh[5], ubh[6], ubh[7], base + GU_UH + bo1);
            LDSM_X4(ubl[0], ubl[1], ubl[2], ubl[3], base + GU_UL + bo0);
            LDSM_X4(ubl[4], ubl[5], ubl[6], ubl[7], base + GU_UL + bo1);
            #pragma unroll
            for (int mt = 0; mt < 2; mt++) {
                #pragma unroll
                for (int nt = 0; nt < 4; nt++) {
                    MMA16816(accg[mt][nt], ah[mt], gbh[2*nt], gbh[2*nt+1]);
                    MMA16816(accg[mt][nt], ah[mt], gbl[2*nt], gbl[2*nt+1]);
                    MMA16816(accg[mt][nt], al[mt], gbh[2*nt], gbh[2*nt+1]);
                    MMA16816(accu[mt][nt], ah[mt], ubh[2*nt], ubh[2*nt+1]);
                    MMA16816(accu[mt][nt], ah[mt], ubl[2*nt], ubl[2*nt+1]);
                    MMA16816(accu[mt][nt], al[mt], ubh[2*nt], ubh[2*nt+1]);
                }
            }
        }
        __syncthreads();
    }

    // SwiGLU epilogue -> bf16 hi/lo
    const int g = lane >> 2, tig = lane & 3;
    #pragma unroll
    for (int mt = 0; mt < 2; mt++) {
        #pragma unroll
        for (int nt = 0; nt < 4; nt++) {
            int r1 = m0 + mw + mt*16 + g;
            int col = n0 + nw + nt*8 + 2*tig;
            {
                float gv0 = accg[mt][nt][0], gv1 = accg[mt][nt][1];
                float h0 = accu[mt][nt][0] * gv0 / (1.f + expf(-gv0));
                float h1 = accu[mt][nt][1] * gv1 / (1.f + expf(-gv1));
                uint32_t lo, hi = pack2(h0, h1, lo);
                *(uint32_t*)(Chi + (size_t)r1 * CLD + col) = hi;
                *(uint32_t*)(Clo + (size_t)r1 * CLD + col) = lo;
            }
            {
                float gv0 = accg[mt][nt][2], gv1 = accg[mt][nt][3];
                float h0 = accu[mt][nt][2] * gv0 / (1.f + expf(-gv0));
                float h1 = accu[mt][nt][3] * gv1 / (1.f + expf(-gv1));
                uint32_t lo, hi = pack2(h0, h1, lo);
                *(uint32_t*)(Chi + (size_t)(r1 + 8) * CLD + col) = hi;
                *(uint32_t*)(Clo + (size_t)(r1 + 8) * CLD + col) = lo;
            }
        }
    }
}

// ============ down GEMM (mma.sync bf16 3-pass), A already bf16 hi/lo ============
// CTA 128x128, warp tile 64x32.
template<int ROUTED>
__global__ void __launch_bounds__(256)
dn_k(const __nv_bfloat16* __restrict__ Ah0, const __nv_bfloat16* __restrict__ Al0,
     const __nv_bfloat16* __restrict__ Bh0, const __nv_bfloat16* __restrict__ Bl0,
     float* __restrict__ C)
{
    constexpr int K  = ROUTED ? IM : ISH;
    constexpr int NS = K / BK;              // 22 or 44
    extern __shared__ char smem[];
    const uint32_t sb = smem_to_u32(smem);
    const int tid = threadIdx.x, wid = tid >> 5, lane = tid & 31;
    const int m0 = blockIdx.x * BM, n0 = blockIdx.y * 128;

    const __nv_bfloat16 *bh = Bh0, *bl = Bl0;
    if (ROUTED) {
        int e = d_tile_e[blockIdx.x];
        if (e < 0) return;
        size_t eo = (size_t)e * HD * IM;
        bh += eo; bl += eo;
    }

    const int rb  = tid >> 3;
    const int chB = (tid & 7) * 16;
    const int chE = (tid & 7) * 8;

    auto copy = [&](int s, int buf) {
        char* bb = smem + (size_t)buf * DN_STAGE;
        const size_t ke = (size_t)s * BK + chE;
        #pragma unroll
        for (int i = 0; i < 4; i++) {
            int r = rb + i * 32;
            uint32_t sw = SMEM_SWIZZLE_128B((uint32_t)(r * 128 + chB));
            size_t ao = (size_t)(m0 + r) * K + ke;
            size_t go = (size_t)(n0 + r) * K + ke;
            *(uint4*)(bb + DN_AH + sw) = *(const uint4*)(Ah0 + ao);
            *(uint4*)(bb + DN_AL + sw) = *(const uint4*)(Al0 + ao);
            *(uint4*)(bb + DN_BH + sw) = *(const uint4*)(bh + go);
            *(uint4*)(bb + DN_BL + sw) = *(const uint4*)(bl + go);
        }
    };

    // warp mapping: 2(m) x 4(n)
    const int mw = (wid & 1) * 64, nw = (wid >> 1) * 32;
    const int arow = mw + (lane & 15);
    const int acs  = lane >> 4;
    const int brow = nw + (lane & 7) + ((lane & 16) ? 8 : 0);
    const int bcs  = (lane >> 3) & 1;

    float acc[4][4][4] = {};

    copy(0, 0);
    __syncthreads();
    for (int s = 0; s < NS; s++) {
        const int b = s & 1;
        if (s + 1 < NS) copy(s + 1, b ^ 1);
        const uint32_t base = sb + b * DN_STAGE;
        #pragma unroll
        for (int k = 0; k < 4; k++) {
            uint32_t ah[4][4], al[4][4];
            #pragma unroll
            for (int mt = 0; mt < 4; mt++) {
                uint32_t off = SMEM_SWIZZLE_128B((uint32_t)((arow + mt*16) * 128 + (2*k + acs) * 16));
                LDSM_X4(ah[mt][0], ah[mt][1], ah[mt][2], ah[mt][3], base + DN_AH + off);
                LDSM_X4(al[mt][0], al[mt][1], al[mt][2], al[mt][3], base + DN_AL + off);
            }
            uint32_t bo0 = SMEM_SWIZZLE_128B((uint32_t)(brow        * 128 + (2*k + bcs) * 16));
            uint32_t bo1 = SMEM_SWIZZLE_128B((uint32_t)((brow + 16) * 128 + (2*k + bcs) * 16));
            uint32_t bbh[8], bbl[8];
            LDSM_X4(bbh[0], bbh[1], bbh[2], bbh[3], base + DN_BH + bo0);
            LDSM_X4(bbh[4], bbh[5], bbh[6], bbh[7], base + DN_BH + bo1);
            LDSM_X4(bbl[0], bbl[1], bbl[2], bbl[3], base + DN_BL + bo0);
            LDSM_X4(bbl[4], bbl[5], bbl[6], bbl[7], base + DN_BL + bo1);
            #pragma unroll
            for (int mt = 0; mt < 4; mt++) {
                #pragma unroll
                for (int nt = 0; nt < 4; nt++) {
                    MMA16816(acc[mt][nt], ah[mt], bbh[2*nt], bbh[2*nt+1]);
                    MMA16816(acc[mt][nt], ah[mt], bbl[2*nt], bbl[2*nt+1]);
                    MMA16816(acc[mt][nt], al[mt], bbh[2*nt], bbh[2*nt+1]);
                }
            }
        }
        __syncthreads();
    }

    const int g = lane >> 2, tig = lane & 3;
    #pragma unroll
    for (int mt = 0; mt < 4; mt++) {
        #pragma unroll
        for (int nt = 0; nt < 4; nt++) {
            int r1 = m0 + mw + mt*16 + g;
            int col = n0 + nw + nt*8 + 2*tig;
            *(float2*)(C + (size_t)r1 * HD + col)       = make_float2(acc[mt][nt][0], acc[mt][nt][1]);
            *(float2*)(C + (size_t)(r1 + 8) * HD + col) = make_float2(acc[mt][nt][2], acc[mt][nt][3]);
        }
    }
}

// ---------------- combine: out += w0*yp[p0] + w1*yp[p1] ----------------
__global__ void combine_k(float* __restrict__ out)
{
    size_t n = (size_t)T * HD;
    size_t stride = (size_t)gridDim.x * blockDim.x;
    for (size_t i = (size_t)blockIdx.x * blockDim.x + threadIdx.x; i < n; i += stride) {
        int t   = (int)(i >> 11);
        int col = (int)(i & 2047);
        int   p0 = d_pslot[2*t],  p1 = d_pslot[2*t+1];
        float w0 = d_topk_w[2*t], w1 = d_topk_w[2*t+1];
        out[i] += w0 * d_yp[(size_t)p0*HD + col] + w1 * d_yp[(size_t)p1*HD + col];
    }
}

// ---------------- launch ----------------
extern "C" void kernel_launch(void* const* d_in, const int* in_sizes, int n_in,
                              void* d_out, int out_size)
{
    const float* x    = (const float*)d_in[0];
    const float* rw   = (const float*)d_in[1];
    const float* bias = (const float*)d_in[2];
    const float* gw   = (const float*)d_in[3];
    const float* uw   = (const float*)d_in[4];
    const float* dw   = (const float*)d_in[5];
    const float* sgw  = (const float*)d_in[6];
    const float* suw  = (const float*)d_in[7];
    const float* sdw  = (const float*)d_in[8];
    float* out = (float*)d_out;

    __nv_bfloat16 *wgh, *wgl, *wuh, *wul, *wdh, *wdl;
    __nv_bfloat16 *sgh, *sgl, *suh, *sul, *sdh, *sdl;
    __nv_bfloat16 *xh, *xl, *hh, *hl, *shh, *shl;
    float* yp;
    cudaGetSymbolAddress((void**)&wgh, w_g_h);  cudaGetSymbolAddress((void**)&wgl, w_g_l);
    cudaGetSymbolAddress((void**)&wuh, w_u_h);  cudaGetSymbolAddress((void**)&wul, w_u_l);
    cudaGetSymbolAddress((void**)&wdh, w_d_h);  cudaGetSymbolAddress((void**)&wdl, w_d_l);
    cudaGetSymbolAddress((void**)&sgh, w_sg_h); cudaGetSymbolAddress((void**)&sgl, w_sg_l);
    cudaGetSymbolAddress((void**)&suh, w_su_h); cudaGetSymbolAddress((void**)&sul, w_su_l);
    cudaGetSymbolAddress((void**)&sdh, w_sd_h); cudaGetSymbolAddress((void**)&sdl, w_sd_l);
    cudaGetSymbolAddress((void**)&xh,  x_hi);   cudaGetSymbolAddress((void**)&xl,  x_lo);
    cudaGetSymbolAddress((void**)&hh,  h_hi);   cudaGetSymbolAddress((void**)&hl,  h_lo);
    cudaGetSymbolAddress((void**)&shh, sh_hi);  cudaGetSymbolAddress((void**)&shl, sh_lo);
    cudaGetSymbolAddress((void**)&yp,  d_yp);

    cudaFuncSetAttribute(gu_k<1>, cudaFuncAttributeMaxDynamicSharedMemorySize, SMEM_BYTES);
    cudaFuncSetAttribute(gu_k<0>, cudaFuncAttributeMaxDynamicSharedMemorySize, SMEM_BYTES);
    cudaFuncSetAttribute(dn_k<1>, cudaFuncAttributeMaxDynamicSharedMemorySize, SMEM_BYTES);
    cudaFuncSetAttribute(dn_k<0>, cudaFuncAttributeMaxDynamicSharedMemorySize, SMEM_BYTES);

    // pre-split weights + x into bf16 hi/lo planes
    split_k<<<2048, 256>>>(gw,  wgh, wgl, (size_t)E*IM*HD/4);
    split_k<<<2048, 256>>>(uw,  wuh, wul, (size_t)E*IM*HD/4);
    split_k<<<2048, 256>>>(dw,  wdh, wdl, (size_t)E*HD*IM/4);
    split_k<<<1024, 256>>>(sgw, sgh, sgl, (size_t)ISH*HD/4);
    split_k<<<1024, 256>>>(suw, suh, sul, (size_t)ISH*HD/4);
    split_k<<<1024, 256>>>(sdw, sdh, sdl, (size_t)HD*ISH/4);
    split_k<<<512,  256>>>(x,   xh,  xl,  (size_t)T*HD/4);

    router_k<<<T, 256>>>(x, rw, bias);
    build_pairs_k<<<1, 256>>>();

    // routed experts
    gu_k<1><<<dim3(NTILES, IM/64),  256, SMEM_BYTES>>>(xh, xl, wgh, wgl, wuh, wul, hh, hl);
    dn_k<1><<<dim3(NTILES, HD/128), 256, SMEM_BYTES>>>(hh, hl, wdh, wdl, yp);

    // shared expert
    gu_k<0><<<dim3(T/BM, ISH/64),  256, SMEM_BYTES>>>(xh, xl, sgh, sgl, suh, sul, shh, shl);
    dn_k<0><<<dim3(T/BM, HD/128),  256, SMEM_BYTES>>>(shh, shl, sdh, sdl, out);

    combine_k<<<2048, 256>>>(out);
}

// round 8
// speedup vs baseline: 2.3020x; 1.0115x over previous
#include <cuda_runtime.h>
#include <cuda_bf16.h>
#include <cstdint>
#include <math.h>

// ---------------- problem constants ----------------
#define T     2048
#define HD    2048          // hidden
#define E     8             // routed experts
#define IM    1408          // moe intermediate
#define ISH   2816          // shared intermediate
#define BM    128
#define BK    64            // bf16 k elems per stage (=128B rows)
#define MAXP  (2*T + E*BM)  // 5120 padded pair rows
#define NTILES (MAXP/BM)    // 40

// gu stage smem layout (bytes)
#define GU_AH 0
#define GU_AL 16384
#define GU_GH 32768
#define GU_GL 40960
#define GU_UH 49152
#define GU_UL 57344
#define GU_STAGE 65536
// down stage layout
#define DN_AH 0
#define DN_AL 16384
#define DN_BH 32768
#define DN_BL 49152
#define DN_STAGE 65536
#define SMEM_BYTES (2*GU_STAGE)   // 131072 for both kernels

#define SMEM_SWIZZLE_128B(off) ((off) ^ (((off) >> 3) & 0x70))

__device__ __forceinline__ uint32_t smem_to_u32(const void* p) {
    uint32_t a;
    asm("{ .reg .u64 t; cvta.to.shared.u64 t, %1; cvt.u32.u64 %0, t; }" : "=r"(a) : "l"(p));
    return a;
}

#define CP_ASYNC16(dst_u32, src_ptr) \
    asm volatile("cp.async.cg.shared.global [%0], [%1], 16;" :: "r"(dst_u32), "l"(src_ptr))
#define CP_ASYNC_WAIT_ALL() asm volatile("cp.async.wait_all;" ::: "memory")

#define LDSM_X4(d0,d1,d2,d3,a) \
    asm volatile("ldmatrix.sync.aligned.m8n8.x4.shared.b16 {%0,%1,%2,%3}, [%4];" \
        : "=r"(d0), "=r"(d1), "=r"(d2), "=r"(d3) : "r"(a))

#define MMA16816(d, a, b0, b1) \
    asm volatile("mma.sync.aligned.m16n8k16.row.col.f32.bf16.bf16.f32 " \
        "{%0,%1,%2,%3}, {%4,%5,%6,%7}, {%8,%9}, {%0,%1,%2,%3};" \
        : "+f"((d)[0]), "+f"((d)[1]), "+f"((d)[2]), "+f"((d)[3]) \
        : "r"((a)[0]), "r"((a)[1]), "r"((a)[2]), "r"((a)[3]), "r"(b0), "r"(b1))

// fp32 -> bf16 hi/lo split of two consecutive values, packed bf16x2
__device__ __forceinline__ uint32_t pack2(float x, float y, uint32_t& lob) {
    __nv_bfloat162 h = __float22bfloat162_rn(make_float2(x, y));
    float2 hf = __bfloat1622float2(h);
    __nv_bfloat162 l = __float22bfloat162_rn(make_float2(x - hf.x, y - hf.y));
    lob = *reinterpret_cast<uint32_t*>(&l);
    return *reinterpret_cast<uint32_t*>(&h);
}

// ---------------- device scratch (static) ----------------
__device__ int   d_topk_idx[2*T];
__device__ float d_topk_w[2*T];
__device__ int   d_cnt[E];
__device__ int   d_off[E];
__device__ int   d_tile_e[NTILES];
__device__ int   d_ptok[MAXP];
__device__ int   d_pslot[2*T];
__device__ __nv_bfloat16 x_hi[(size_t)T*HD],    x_lo[(size_t)T*HD];
__device__ __nv_bfloat16 h_hi[(size_t)MAXP*IM], h_lo[(size_t)MAXP*IM];
__device__ __nv_bfloat16 sh_hi[(size_t)T*ISH],  sh_lo[(size_t)T*ISH];
__device__ float d_yp[(size_t)MAXP*HD];

// ---------------- split: fp32 -> bf16 hi + lo (x only) ----------------
__global__ void split_k(const float* __restrict__ s,
                        __nv_bfloat16* __restrict__ hi, __nv_bfloat16* __restrict__ lo,
                        size_t n4)
{
    size_t stride = (size_t)gridDim.x * blockDim.x;
    const float4* s4 = (const float4*)s;
    uint2* h2 = (uint2*)hi;
    uint2* l2 = (uint2*)lo;
    for (size_t i = (size_t)blockIdx.x * blockDim.x + threadIdx.x; i < n4; i += stride) {
        float4 v = s4[i];
        uint32_t l0, l1;
        uint32_t h0 = pack2(v.x, v.y, l0);
        uint32_t h1 = pack2(v.z, v.w, l1);
        h2[i] = make_uint2(h0, h1);
        l2[i] = make_uint2(l0, l1);
    }
}

// ---------------- router ----------------
__global__ void router_k(const float* __restrict__ x,
                         const float* __restrict__ rw,
                         const float* __restrict__ bias)
{
    __shared__ float xs[HD];
    __shared__ float logits[E];
    int t = blockIdx.x, tid = threadIdx.x;
    for (int i = tid; i < HD; i += blockDim.x) xs[i] = x[(size_t)t*HD + i];
    __syncthreads();
    int wid = tid >> 5, lane = tid & 31;
    if (wid < E) {
        float s = 0.f;
        for (int k = lane; k < HD; k += 32) s += xs[k] * rw[wid*HD + k];
        #pragma unroll
        for (int o = 16; o; o >>= 1) s += __shfl_down_sync(0xffffffffu, s, o);
        if (!lane) logits[wid] = s;
    }
    __syncthreads();
    if (tid == 0) {
        float sc[E], sfc[E];
        #pragma unroll
        for (int e = 0; e < E; e++) {
            sc[e]  = 1.f / (1.f + expf(-logits[e]));
            sfc[e] = sc[e] + bias[e];
        }
        float gs[4];
        #pragma unroll
        for (int g = 0; g < 4; g++) gs[g] = sfc[2*g] + sfc[2*g+1];
        int g1 = 0;
        #pragma unroll
        for (int g = 1; g < 4; g++) if (gs[g] > gs[g1]) g1 = g;
        int g2 = -1;
        #pragma unroll
        for (int g = 0; g < 4; g++) { if (g == g1) continue; if (g2 < 0 || gs[g] > gs[g2]) g2 = g; }
        float masked[E];
        #pragma unroll
        for (int e = 0; e < E; e++) { int g = e >> 1; masked[e] = (g == g1 || g == g2) ? sfc[e] : 0.f; }
        int i1 = 0;
        #pragma unroll
        for (int e = 1; e < E; e++) if (masked[e] > masked[i1]) i1 = e;
        int i2 = -1;
        #pragma unroll
        for (int e = 0; e < E; e++) { if (e == i1) continue; if (i2 < 0 || masked[e] > masked[i2]) i2 = e; }
        float w1 = sc[i1], w2 = sc[i2];
        float inv = 2.5f / (w1 + w2 + 1e-20f);
        d_topk_idx[2*t] = i1; d_topk_idx[2*t+1] = i2;
        d_topk_w[2*t]   = w1 * inv;
        d_topk_w[2*t+1] = w2 * inv;
    }
}

// ---------------- deterministic pair list ----------------
__global__ void build_pairs_k()
{
    __shared__ int cnts[E], offs[E];
    int tid = threadIdx.x, wid = tid >> 5, lane = tid & 31;
    for (int i = tid; i < MAXP; i += blockDim.x) d_ptok[i] = 0;  // padded rows -> token 0
    if (wid < E) {
        int c = 0;
        for (int base = 0; base < T; base += 32) {
            int t = base + lane;
            bool sel = (d_topk_idx[2*t] == wid) || (d_topk_idx[2*t+1] == wid);
            c += __popc(__ballot_sync(0xffffffffu, sel));
        }
        if (!lane) cnts[wid] = c;
    }
    __syncthreads();
    if (tid == 0) {
        int o = 0;
        for (int e = 0; e < E; e++) {
            offs[e] = o; d_off[e] = o; d_cnt[e] = cnts[e];
            o += ((cnts[e] + BM - 1) / BM) * BM;
        }
        int tcur = 0;
        for (int e = 0; e < E; e++) {
            int t0 = offs[e] / BM, nt = (cnts[e] + BM - 1) / BM;
            for (int i = 0; i < nt; i++) d_tile_e[t0 + i] = e;
            tcur = t0 + nt;
        }
        for (int i = tcur; i < NTILES; i++) d_tile_e[i] = -1;
    }
    __syncthreads();
    if (wid < E) {
        int pos = offs[wid];
        for (int base = 0; base < T; base += 32) {
            int t = base + lane;
            int e0 = d_topk_idx[2*t], e1 = d_topk_idx[2*t+1];
            int j = (e0 == wid) ? 0 : ((e1 == wid) ? 1 : -1);
            unsigned m = __ballot_sync(0xffffffffu, j >= 0);
            if (j >= 0) {
                int p = pos + __popc(m & ((1u << lane) - 1u));
                d_ptok[p] = t;
                d_pslot[2*t+j] = p;
            }
            pos += __popc(m);
        }
    }
}

// store 8 fp32 (2 float4) as swizzled bf16 hi/lo (two 8B stores per plane)
__device__ __forceinline__ void cvt_store8(const float* gsrc, char* hibase, char* lobase,
                                           int row, int c2)  // c2 = even fp32-chunk idx (0,2,..,14)
{
    float4 a = __ldg((const float4*)(gsrc));
    float4 b = __ldg(((const float4*)(gsrc)) + 1);
    uint32_t l0, l1, l2, l3;
    uint32_t h0 = pack2(a.x, a.y, l0);
    uint32_t h1 = pack2(a.z, a.w, l1);
    uint32_t h2 = pack2(b.x, b.y, l2);
    uint32_t h3 = pack2(b.z, b.w, l3);
    uint32_t sw = SMEM_SWIZZLE_128B((uint32_t)(row * 128 + c2 * 8));
    *(uint4*)(hibase + sw) = make_uint4(h0, h1, h2, h3);
    *(uint4*)(lobase + sw) = make_uint4(l0, l1, l2, l3);
}

// ============ fused gate+up GEMM (mma.sync bf16 3-pass) + SwiGLU epilogue ============
// CTA 128x64, K = HD. Weights arrive fp32, converted in the copy loop.
template<int ROUTED>
__global__ void __launch_bounds__(256)
gu_k(const __nv_bfloat16* __restrict__ Xh, const __nv_bfloat16* __restrict__ Xl,
     const float* __restrict__ Gw0, const float* __restrict__ Uw0,
     __nv_bfloat16* __restrict__ Chi, __nv_bfloat16* __restrict__ Clo)
{
    constexpr int NS  = HD / BK;            // 32
    constexpr int CLD = ROUTED ? IM : ISH;
    extern __shared__ char smem[];
    const uint32_t sb = smem_to_u32(smem);
    const int tid = threadIdx.x, wid = tid >> 5, lane = tid & 31;
    const int m0 = blockIdx.x * BM, n0 = blockIdx.y * 64;

    const float *gw = Gw0, *uw = Uw0;
    if (ROUTED) {
        int e = d_tile_e[blockIdx.x];
        if (e < 0) return;
        size_t eo = (size_t)e * IM * HD;
        gw += eo; uw += eo;
    }

    // A-plane copy descriptors (cp.async): rb row base, chB/chE chunk in row
    const int rb  = tid >> 3;               // 0..31
    const int chB = (tid & 7) * 16;
    const int chE = (tid & 7) * 8;
    const __nv_bfloat16 *axh[4], *axl[4];
    uint32_t aswz[4];
    #pragma unroll
    for (int i = 0; i < 4; i++) {
        int r = rb + i * 32;
        int gr = m0 + r;
        int srow = ROUTED ? d_ptok[gr] : gr;
        aswz[i] = SMEM_SWIZZLE_128B((uint32_t)(r * 128 + chB));
        axh[i] = Xh + (size_t)srow * HD + chE;
        axl[i] = Xl + (size_t)srow * HD + chE;
    }
    // B-side (fp32 weights): row 0..63, 4 threads/row, 2 double-chunks each
    const int brow_ld = tid >> 2;           // 0..63
    const int bc0     = (tid & 3) * 4;      // even chunk base: 0,4,8,12

    auto copy = [&](int s, int buf) {
        char* bb = smem + (size_t)buf * GU_STAGE;
        const uint32_t bs = sb + (uint32_t)buf * GU_STAGE;
        const size_t ke = (size_t)s * BK + chE;   // bf16 elem offset for A
        #pragma unroll
        for (int i = 0; i < 4; i++) {
            CP_ASYNC16(bs + GU_AH + aswz[i], axh[i] + s * BK);
            CP_ASYNC16(bs + GU_AL + aswz[i], axl[i] + s * BK);
        }
        const size_t gofs = (size_t)(n0 + brow_ld) * HD + s * BK;
        cvt_store8(gw + gofs + bc0 * 4,       bb + GU_GH, bb + GU_GL, brow_ld, bc0);
        cvt_store8(gw + gofs + (bc0 + 2) * 4, bb + GU_GH, bb + GU_GL, brow_ld, bc0 + 2);
        cvt_store8(uw + gofs + bc0 * 4,       bb + GU_UH, bb + GU_UL, brow_ld, bc0);
        cvt_store8(uw + gofs + (bc0 + 2) * 4, bb + GU_UH, bb + GU_UL, brow_ld, bc0 + 2);
        (void)ke;
    };

    // warp mapping: 4(m) x 2(n)
    const int mw = (wid & 3) * 32, nw = (wid >> 2) * 32;
    const int arow = mw + (lane & 15);
    const int acs  = lane >> 4;
    const int brow = nw + (lane & 7) + ((lane & 16) ? 8 : 0);
    const int bcs  = (lane >> 3) & 1;

    float accg[2][4][4] = {}, accu[2][4][4] = {};

    copy(0, 0);
    CP_ASYNC_WAIT_ALL();
    __syncthreads();
    for (int s = 0; s < NS; s++) {
        const int b = s & 1;
        if (s + 1 < NS) copy(s + 1, b ^ 1);
        const uint32_t base = sb + b * GU_STAGE;
        #pragma unroll
        for (int k = 0; k < 4; k++) {
            uint32_t ah[2][4], al[2][4];
            #pragma unroll
            for (int mt = 0; mt < 2; mt++) {
                uint32_t off = SMEM_SWIZZLE_128B((uint32_t)((arow + mt*16) * 128 + (2*k + acs) * 16));
                LDSM_X4(ah[mt][0], ah[mt][1], ah[mt][2], ah[mt][3], base + GU_AH + off);
                LDSM_X4(al[mt][0], al[mt][1], al[mt][2], al[mt][3], base + GU_AL + off);
            }
            uint32_t bo0 = SMEM_SWIZZLE_128B((uint32_t)(brow        * 128 + (2*k + bcs) * 16));
            uint32_t bo1 = SMEM_SWIZZLE_128B((uint32_t)((brow + 16) * 128 + (2*k + bcs) * 16));
            uint32_t gbh[8], gbl[8], ubh[8], ubl[8];
            LDSM_X4(gbh[0], gbh[1], gbh[2], gbh[3], base + GU_GH + bo0);
            LDSM_X4(gbh[4], gbh[5], gbh[6], gbh[7], base + GU_GH + bo1);
            LDSM_X4(gbl[0], gbl[1], gbl[2], gbl[3], base + GU_GL + bo0);
            LDSM_X4(gbl[4], gbl[5], gbl[6], gbl[7], base + GU_GL + bo1);
            LDSM_X4(ubh[0], ubh[1], ubh[2], ubh[3], base + GU_UH + bo0);
            LDSM_X4(ubh[4], ubh[5], ubh[6], ubh[7], base + GU_UH + bo1);
            LDSM_X4(ubl[0], ubl[1], ubl[2], ubl[3], base + GU_UL + bo0);
            LDSM_X4(ubl[4], ubl[5], ubl[6], ubl[7], base + GU_UL + bo1);
            #pragma unroll
            for (int mt = 0; mt < 2; mt++) {
                #pragma unroll
                for (int nt = 0; nt < 4; nt++) {
                    MMA16816(accg[mt][nt], ah[mt], gbh[2*nt], gbh[2*nt+1]);
                    MMA16816(accg[mt][nt], ah[mt], gbl[2*nt], gbl[2*nt+1]);
                    MMA16816(accg[mt][nt], al[mt], gbh[2*nt], gbh[2*nt+1]);
                    MMA16816(accu[mt][nt], ah[mt], ubh[2*nt], ubh[2*nt+1]);
                    MMA16816(accu[mt][nt], ah[mt], ubl[2*nt], ubl[2*nt+1]);
                    MMA16816(accu[mt][nt], al[mt], ubh[2*nt], ubh[2*nt+1]);
                }
            }
        }
        CP_ASYNC_WAIT_ALL();
        __syncthreads();
    }

    // SwiGLU epilogue -> bf16 hi/lo
    const int g = lane >> 2, tig = lane & 3;
    #pragma unroll
    for (int mt = 0; mt < 2; mt++) {
        #pragma unroll
        for (int nt = 0; nt < 4; nt++) {
            int r1 = m0 + mw + mt*16 + g;
            int col = n0 + nw + nt*8 + 2*tig;
            {
                float gv0 = accg[mt][nt][0], gv1 = accg[mt][nt][1];
                float h0 = accu[mt][nt][0] * gv0 / (1.f + expf(-gv0));
                float h1 = accu[mt][nt][1] * gv1 / (1.f + expf(-gv1));
                uint32_t lo, hi = pack2(h0, h1, lo);
                *(uint32_t*)(Chi + (size_t)r1 * CLD + col) = hi;
                *(uint32_t*)(Clo + (size_t)r1 * CLD + col) = lo;
            }
            {
                float gv0 = accg[mt][nt][2], gv1 = accg[mt][nt][3];
                float h0 = accu[mt][nt][2] * gv0 / (1.f + expf(-gv0));
                float h1 = accu[mt][nt][3] * gv1 / (1.f + expf(-gv1));
                uint32_t lo, hi = pack2(h0, h1, lo);
                *(uint32_t*)(Chi + (size_t)(r1 + 8) * CLD + col) = hi;
                *(uint32_t*)(Clo + (size_t)(r1 + 8) * CLD + col) = lo;
            }
        }
    }
}

// ============ down GEMM (mma.sync bf16 3-pass), A bf16 hi/lo, B fp32 converted in-kernel ============
// CTA 128x128, warp tile 64x32.
template<int ROUTED>
__global__ void __launch_bounds__(256)
dn_k(const __nv_bfloat16* __restrict__ Ah0, const __nv_bfloat16* __restrict__ Al0,
     const float* __restrict__ Bw0, float* __restrict__ C)
{
    constexpr int K  = ROUTED ? IM : ISH;
    constexpr int NS = K / BK;              // 22 or 44
    extern __shared__ char smem[];
    const uint32_t sb = smem_to_u32(smem);
    const int tid = threadIdx.x, wid = tid >> 5, lane = tid & 31;
    const int m0 = blockIdx.x * BM, n0 = blockIdx.y * 128;

    const float* bw = Bw0;
    if (ROUTED) {
        int e = d_tile_e[blockIdx.x];
        if (e < 0) return;
        bw += (size_t)e * HD * IM;
    }

    const int rb  = tid >> 3;
    const int chB = (tid & 7) * 16;
    const int chE = (tid & 7) * 8;
    uint32_t aswz[4];
    const __nv_bfloat16 *aah[4], *aal[4];
    #pragma unroll
    for (int i = 0; i < 4; i++) {
        int r = rb + i * 32;
        aswz[i] = SMEM_SWIZZLE_128B((uint32_t)(r * 128 + chB));
        aah[i] = Ah0 + (size_t)(m0 + r) * K + chE;
        aal[i] = Al0 + (size_t)(m0 + r) * K + chE;
    }
    // B-side: 128 rows, 2 threads/row, 4 double-chunks each
    const int brow_ld = tid >> 1;           // 0..127
    const int bc0     = (tid & 1) * 8;      // 0 or 8

    auto copy = [&](int s, int buf) {
        char* bb = smem + (size_t)buf * DN_STAGE;
        const uint32_t bs = sb + (uint32_t)buf * DN_STAGE;
        #pragma unroll
        for (int i = 0; i < 4; i++) {
            CP_ASYNC16(bs + DN_AH + aswz[i], aah[i] + s * BK);
            CP_ASYNC16(bs + DN_AL + aswz[i], aal[i] + s * BK);
        }
        const size_t gofs = (size_t)(n0 + brow_ld) * K + s * BK;
        #pragma unroll
        for (int j = 0; j < 4; j++) {
            int c2 = bc0 + 2 * j;
            cvt_store8(bw + gofs + c2 * 4, bb + DN_BH, bb + DN_BL, brow_ld, c2);
        }
    };

    // warp mapping: 2(m) x 4(n)
    const int mw = (wid & 1) * 64, nw = (wid >> 1) * 32;
    const int arow = mw + (lane & 15);
    const int acs  = lane >> 4;
    const int brow = nw + (lane & 7) + ((lane & 16) ? 8 : 0);
    const int bcs  = (lane >> 3) & 1;

    float acc[4][4][4] = {};

    copy(0, 0);
    CP_ASYNC_WAIT_ALL();
    __syncthreads();
    for (int s = 0; s < NS; s++) {
        const int b = s & 1;
        if (s + 1 < NS) copy(s + 1, b ^ 1);
        const uint32_t base = sb + b * DN_STAGE;
        #pragma unroll
        for (int k = 0; k < 4; k++) {
            uint32_t ah[4][4], al[4][4];
            #pragma unroll
            for (int mt = 0; mt < 4; mt++) {
                uint32_t off = SMEM_SWIZZLE_128B((uint32_t)((arow + mt*16) * 128 + (2*k + acs) * 16));
                LDSM_X4(ah[mt][0], ah[mt][1], ah[mt][2], ah[mt][3], base + DN_AH + off);
                LDSM_X4(al[mt][0], al[mt][1], al[mt][2], al[mt][3], base + DN_AL + off);
            }
            uint32_t bo0 = SMEM_SWIZZLE_128B((uint32_t)(brow        * 128 + (2*k + bcs) * 16));
            uint32_t bo1 = SMEM_SWIZZLE_128B((uint32_t)((brow + 16) * 128 + (2*k + bcs) * 16));
            uint32_t bbh[8], bbl[8];
            LDSM_X4(bbh[0], bbh[1], bbh[2], bbh[3], base + DN_BH + bo0);
            LDSM_X4(bbh[4], bbh[5], bbh[6], bbh[7], base + DN_BH + bo1);
            LDSM_X4(bbl[0], bbl[1], bbl[2], bbl[3], base + DN_BL + bo0);
            LDSM_X4(bbl[4], bbl[5], bbl[6], bbl[7], base + DN_BL + bo1);
            #pragma unroll
            for (int mt = 0; mt < 4; mt++) {
                #pragma unroll
                for (int nt = 0; nt < 4; nt++) {
                    MMA16816(acc[mt][nt], ah[mt], bbh[2*nt], bbh[2*nt+1]);
                    MMA16816(acc[mt][nt], ah[mt], bbl[2*nt], bbl[2*nt+1]);
                    MMA16816(acc[mt][nt], al[mt], bbh[2*nt], bbh[2*nt+1]);
                }
            }
        }
        CP_ASYNC_WAIT_ALL();
        __syncthreads();
    }

    const int g = lane >> 2, tig = lane & 3;
    #pragma unroll
    for (int mt = 0; mt < 4; mt++) {
        #pragma unroll
        for (int nt = 0; nt < 4; nt++) {
            int r1 = m0 + mw + mt*16 + g;
            int col = n0 + nw + nt*8 + 2*tig;
            *(float2*)(C + (size_t)r1 * HD + col)       = make_float2(acc[mt][nt][0], acc[mt][nt][1]);
            *(float2*)(C + (size_t)(r1 + 8) * HD + col) = make_float2(acc[mt][nt][2], acc[mt][nt][3]);
        }
    }
}

// ---------------- combine: out += w0*yp[p0] + w1*yp[p1] ----------------
__global__ void combine_k(float* __restrict__ out)
{
    size_t n = (size_t)T * HD;
    size_t stride = (size_t)gridDim.x * blockDim.x;
    for (size_t i = (size_t)blockIdx.x * blockDim.x + threadIdx.x; i < n; i += stride) {
        int t   = (int)(i >> 11);
        int col = (int)(i & 2047);
        int   p0 = d_pslot[2*t],  p1 = d_pslot[2*t+1];
        float w0 = d_topk_w[2*t], w1 = d_topk_w[2*t+1];
        out[i] += w0 * d_yp[(size_t)p0*HD + col] + w1 * d_yp[(size_t)p1*HD + col];
    }
}

// ---------------- launch ----------------
extern "C" void kernel_launch(void* const* d_in, const int* in_sizes, int n_in,
                              void* d_out, int out_size)
{
    const float* x    = (const float*)d_in[0];
    const float* rw   = (const float*)d_in[1];
    const float* bias = (const float*)d_in[2];
    const float* gw   = (const float*)d_in[3];
    const float* uw   = (const float*)d_in[4];
    const float* dw   = (const float*)d_in[5];
    const float* sgw  = (const float*)d_in[6];
    const float* suw  = (const float*)d_in[7];
    const float* sdw  = (const float*)d_in[8];
    float* out = (float*)d_out;

    __nv_bfloat16 *xh, *xl, *hh, *hl, *shh, *shl;
    float* yp;
    cudaGetSymbolAddress((void**)&xh,  x_hi);   cudaGetSymbolAddress((void**)&xl,  x_lo);
    cudaGetSymbolAddress((void**)&hh,  h_hi);   cudaGetSymbolAddress((void**)&hl,  h_lo);
    cudaGetSymbolAddress((void**)&shh, sh_hi);  cudaGetSymbolAddress((void**)&shl, sh_lo);
    cudaGetSymbolAddress((void**)&yp,  d_yp);

    cudaFuncSetAttribute(gu_k<1>, cudaFuncAttributeMaxDynamicSharedMemorySize, SMEM_BYTES);
    cudaFuncSetAttribute(gu_k<0>, cudaFuncAttributeMaxDynamicSharedMemorySize, SMEM_BYTES);
    cudaFuncSetAttribute(dn_k<1>, cudaFuncAttributeMaxDynamicSharedMemorySize, SMEM_BYTES);
    cudaFuncSetAttribute(dn_k<0>, cudaFuncAttributeMaxDynamicSharedMemorySize, SMEM_BYTES);

    split_k<<<512, 256>>>(x, xh, xl, (size_t)T*HD/4);
    router_k<<<T, 256>>>(x, rw, bias);
    build_pairs_k<<<1, 256>>>();

    // routed experts
    gu_k<1><<<dim3(NTILES, IM/64),  256, SMEM_BYTES>>>(xh, xl, gw, uw, hh, hl);
    dn_k<1><<<dim3(NTILES, HD/128), 256, SMEM_BYTES>>>(hh, hl, dw, yp);

    // shared expert
    gu_k<0><<<dim3(T/BM, ISH/64),  256, SMEM_BYTES>>>(xh, xl, sgw, suw, shh, shl);
    dn_k<0><<<dim3(T/BM, HD/128),  256, SMEM_BYTES>>>(shh, shl, sdw, out);

    combine_k<<<2048, 256>>>(out);
}

// round 9
// speedup vs baseline: 2.7185x; 1.1809x over previous
#include <cuda_runtime.h>
#include <cuda_bf16.h>
#include <cstdint>
#include <math.h>

// ---------------- problem constants ----------------
#define T     2048
#define HD    2048          // hidden
#define E     8             // routed experts
#define IM    1408          // moe intermediate
#define ISH   2816          // shared intermediate
#define BM    128
#define BK    64            // bf16 k elems per stage (=128B rows)
#define MAXP  (2*T + E*BM)  // 5120 padded pair rows
#define NTILES (MAXP/BM)    // 40

// gu stage smem layout (bytes)
#define GU_AH 0
#define GU_AL 16384
#define GU_GH 32768
#define GU_GL 40960
#define GU_UH 49152
#define GU_UL 57344
#define GU_STAGE 65536
// down stage layout
#define DN_AH 0
#define DN_AL 16384
#define DN_BH 32768
#define DN_BL 49152
#define DN_STAGE 65536
#define SMEM_BYTES (2*GU_STAGE)   // 131072 for both kernels

#define SMEM_SWIZZLE_128B(off) ((off) ^ (((off) >> 3) & 0x70))

__device__ __forceinline__ uint32_t smem_to_u32(const void* p) {
    uint32_t a;
    asm("{ .reg .u64 t; cvta.to.shared.u64 t, %1; cvt.u32.u64 %0, t; }" : "=r"(a) : "l"(p));
    return a;
}

#define CP_ASYNC16(dst_u32, src_ptr) \
    asm volatile("cp.async.cg.shared.global [%0], [%1], 16;" :: "r"(dst_u32), "l"(src_ptr))
#define CP_ASYNC_WAIT_ALL() asm volatile("cp.async.wait_all;" ::: "memory")

#define LDSM_X4(d0,d1,d2,d3,a) \
    asm volatile("ldmatrix.sync.aligned.m8n8.x4.shared.b16 {%0,%1,%2,%3}, [%4];" \
        : "=r"(d0), "=r"(d1), "=r"(d2), "=r"(d3) : "r"(a))

#define MMA16816(d, a, b0, b1) \
    asm volatile("mma.sync.aligned.m16n8k16.row.col.f32.bf16.bf16.f32 " \
        "{%0,%1,%2,%3}, {%4,%5,%6,%7}, {%8,%9}, {%0,%1,%2,%3};" \
        : "+f"((d)[0]), "+f"((d)[1]), "+f"((d)[2]), "+f"((d)[3]) \
        : "r"((a)[0]), "r"((a)[1]), "r"((a)[2]), "r"((a)[3]), "r"(b0), "r"(b1))

// fp32 -> bf16 hi/lo split of two consecutive values, packed bf16x2
__device__ __forceinline__ uint32_t pack2(float x, float y, uint32_t& lob) {
    __nv_bfloat162 h = __float22bfloat162_rn(make_float2(x, y));
    float2 hf = __bfloat1622float2(h);
    __nv_bfloat162 l = __float22bfloat162_rn(make_float2(x - hf.x, y - hf.y));
    lob = *reinterpret_cast<uint32_t*>(&l);
    return *reinterpret_cast<uint32_t*>(&h);
}

// convert two prefetched float4 (8 fp32) -> swizzled bf16 hi/lo 16B stores
__device__ __forceinline__ void cvt_store8_reg(float4 a, float4 b, char* hibase, char* lobase,
                                               int row, int c2)
{
    uint32_t l0, l1, l2, l3;
    uint32_t h0 = pack2(a.x, a.y, l0);
    uint32_t h1 = pack2(a.z, a.w, l1);
    uint32_t h2 = pack2(b.x, b.y, l2);
    uint32_t h3 = pack2(b.z, b.w, l3);
    uint32_t sw = SMEM_SWIZZLE_128B((uint32_t)(row * 128 + c2 * 8));
    *(uint4*)(hibase + sw) = make_uint4(h0, h1, h2, h3);
    *(uint4*)(lobase + sw) = make_uint4(l0, l1, l2, l3);
}

// ---------------- device scratch (static) ----------------
__device__ int   d_topk_idx[2*T];
__device__ float d_topk_w[2*T];
__device__ int   d_cnt[E];
__device__ int   d_off[E];
__device__ int   d_tile_e[NTILES];
__device__ int   d_ptok[MAXP];
__device__ int   d_pslot[2*T];
__device__ __nv_bfloat16 x_hi[(size_t)T*HD],    x_lo[(size_t)T*HD];
__device__ __nv_bfloat16 h_hi[(size_t)MAXP*IM], h_lo[(size_t)MAXP*IM];
__device__ __nv_bfloat16 sh_hi[(size_t)T*ISH],  sh_lo[(size_t)T*ISH];
__device__ float d_yp[(size_t)MAXP*HD];

// ---------------- split: fp32 -> bf16 hi + lo (x only) ----------------
__global__ void split_k(const float* __restrict__ s,
                        __nv_bfloat16* __restrict__ hi, __nv_bfloat16* __restrict__ lo,
                        size_t n4)
{
    size_t stride = (size_t)gridDim.x * blockDim.x;
    const float4* s4 = (const float4*)s;
    uint2* h2 = (uint2*)hi;
    uint2* l2 = (uint2*)lo;
    for (size_t i = (size_t)blockIdx.x * blockDim.x + threadIdx.x; i < n4; i += stride) {
        float4 v = s4[i];
        uint32_t l0, l1;
        uint32_t h0 = pack2(v.x, v.y, l0);
        uint32_t h1 = pack2(v.z, v.w, l1);
        h2[i] = make_uint2(h0, h1);
        l2[i] = make_uint2(l0, l1);
    }
}

// ---------------- router ----------------
__global__ void router_k(const float* __restrict__ x,
                         const float* __restrict__ rw,
                         const float* __restrict__ bias)
{
    __shared__ float xs[HD];
    __shared__ float logits[E];
    int t = blockIdx.x, tid = threadIdx.x;
    for (int i = tid; i < HD; i += blockDim.x) xs[i] = x[(size_t)t*HD + i];
    __syncthreads();
    int wid = tid >> 5, lane = tid & 31;
    if (wid < E) {
        float s = 0.f;
        for (int k = lane; k < HD; k += 32) s += xs[k] * rw[wid*HD + k];
        #pragma unroll
        for (int o = 16; o; o >>= 1) s += __shfl_down_sync(0xffffffffu, s, o);
        if (!lane) logits[wid] = s;
    }
    __syncthreads();
    if (tid == 0) {
        float sc[E], sfc[E];
        #pragma unroll
        for (int e = 0; e < E; e++) {
            sc[e]  = 1.f / (1.f + expf(-logits[e]));
            sfc[e] = sc[e] + bias[e];
        }
        float gs[4];
        #pragma unroll
        for (int g = 0; g < 4; g++) gs[g] = sfc[2*g] + sfc[2*g+1];
        int g1 = 0;
        #pragma unroll
        for (int g = 1; g < 4; g++) if (gs[g] > gs[g1]) g1 = g;
        int g2 = -1;
        #pragma unroll
        for (int g = 0; g < 4; g++) { if (g == g1) continue; if (g2 < 0 || gs[g] > gs[g2]) g2 = g; }
        float masked[E];
        #pragma unroll
        for (int e = 0; e < E; e++) { int g = e >> 1; masked[e] = (g == g1 || g == g2) ? sfc[e] : 0.f; }
        int i1 = 0;
        #pragma unroll
        for (int e = 1; e < E; e++) if (masked[e] > masked[i1]) i1 = e;
        int i2 = -1;
        #pragma unroll
        for (int e = 0; e < E; e++) { if (e == i1) continue; if (i2 < 0 || masked[e] > masked[i2]) i2 = e; }
        float w1 = sc[i1], w2 = sc[i2];
        float inv = 2.5f / (w1 + w2 + 1e-20f);
        d_topk_idx[2*t] = i1; d_topk_idx[2*t+1] = i2;
        d_topk_w[2*t]   = w1 * inv;
        d_topk_w[2*t+1] = w2 * inv;
    }
}

// ---------------- deterministic pair list ----------------
__global__ void build_pairs_k()
{
    __shared__ int cnts[E], offs[E];
    int tid = threadIdx.x, wid = tid >> 5, lane = tid & 31;
    for (int i = tid; i < MAXP; i += blockDim.x) d_ptok[i] = 0;  // padded rows -> token 0
    if (wid < E) {
        int c = 0;
        for (int base = 0; base < T; base += 32) {
            int t = base + lane;
            bool sel = (d_topk_idx[2*t] == wid) || (d_topk_idx[2*t+1] == wid);
            c += __popc(__ballot_sync(0xffffffffu, sel));
        }
        if (!lane) cnts[wid] = c;
    }
    __syncthreads();
    if (tid == 0) {
        int o = 0;
        for (int e = 0; e < E; e++) {
            offs[e] = o; d_off[e] = o; d_cnt[e] = cnts[e];
            o += ((cnts[e] + BM - 1) / BM) * BM;
        }
        int tcur = 0;
        for (int e = 0; e < E; e++) {
            int t0 = offs[e] / BM, nt = (cnts[e] + BM - 1) / BM;
            for (int i = 0; i < nt; i++) d_tile_e[t0 + i] = e;
            tcur = t0 + nt;
        }
        for (int i = tcur; i < NTILES; i++) d_tile_e[i] = -1;
    }
    __syncthreads();
    if (wid < E) {
        int pos = offs[wid];
        for (int base = 0; base < T; base += 32) {
            int t = base + lane;
            int e0 = d_topk_idx[2*t], e1 = d_topk_idx[2*t+1];
            int j = (e0 == wid) ? 0 : ((e1 == wid) ? 1 : -1);
            unsigned m = __ballot_sync(0xffffffffu, j >= 0);
            if (j >= 0) {
                int p = pos + __popc(m & ((1u << lane) - 1u));
                d_ptok[p] = t;
                d_pslot[2*t+j] = p;
            }
            pos += __popc(m);
        }
    }
}

// ============ fused gate+up GEMM (mma.sync bf16 3-pass) + SwiGLU epilogue ============
// CTA 128x64, K = HD. Weight LDGs register-prefetched one stage ahead; cvt after MMAs.
template<int ROUTED>
__global__ void __launch_bounds__(256)
gu_k(const __nv_bfloat16* __restrict__ Xh, const __nv_bfloat16* __restrict__ Xl,
     const float* __restrict__ Gw0, const float* __restrict__ Uw0,
     __nv_bfloat16* __restrict__ Chi, __nv_bfloat16* __restrict__ Clo)
{
    constexpr int NS  = HD / BK;            // 32
    constexpr int CLD = ROUTED ? IM : ISH;
    extern __shared__ char smem[];
    const uint32_t sb = smem_to_u32(smem);
    const int tid = threadIdx.x, wid = tid >> 5, lane = tid & 31;
    const int m0 = blockIdx.x * BM, n0 = blockIdx.y * 64;

    const float *gw = Gw0, *uw = Uw0;
    if (ROUTED) {
        int e = d_tile_e[blockIdx.x];
        if (e < 0) return;
        size_t eo = (size_t)e * IM * HD;
        gw += eo; uw += eo;
    }

    // A-plane cp.async descriptors
    const int rb  = tid >> 3;               // 0..31
    const int chB = (tid & 7) * 16;
    const int chE = (tid & 7) * 8;
    const __nv_bfloat16 *axh[4], *axl[4];
    uint32_t aswz[4];
    #pragma unroll
    for (int i = 0; i < 4; i++) {
        int r = rb + i * 32;
        int gr = m0 + r;
        int srow = ROUTED ? d_ptok[gr] : gr;
        aswz[i] = SMEM_SWIZZLE_128B((uint32_t)(r * 128 + chB));
        axh[i] = Xh + (size_t)srow * HD + chE;
        axl[i] = Xl + (size_t)srow * HD + chE;
    }
    // B-side (fp32 weights): 64 rows, 4 threads/row, 16 consecutive fp32 each
    const int brow_ld = tid >> 2;           // 0..63
    const int bc0     = (tid & 3) * 4;      // chunk base: 0,4,8,12 (fp32 elems = bc0*4)
    const float* gsrc = gw + (size_t)(n0 + brow_ld) * HD + bc0 * 4;
    const float* usrc = uw + (size_t)(n0 + brow_ld) * HD + bc0 * 4;

    auto issueA = [&](int s, int buf) {
        const uint32_t bs = sb + (uint32_t)buf * GU_STAGE;
        #pragma unroll
        for (int i = 0; i < 4; i++) {
            CP_ASYNC16(bs + GU_AH + aswz[i], axh[i] + s * BK);
            CP_ASYNC16(bs + GU_AL + aswz[i], axl[i] + s * BK);
        }
    };
    auto loadB = [&](int s, float4* pg, float4* pu) {
        const float4* g4 = (const float4*)(gsrc + s * BK);
        const float4* u4 = (const float4*)(usrc + s * BK);
        #pragma unroll
        for (int j = 0; j < 4; j++) { pg[j] = __ldg(g4 + j); pu[j] = __ldg(u4 + j); }
    };
    auto storeB = [&](int buf, const float4* pg, const float4* pu) {
        char* bb = smem + (size_t)buf * GU_STAGE;
        cvt_store8_reg(pg[0], pg[1], bb + GU_GH, bb + GU_GL, brow_ld, bc0);
        cvt_store8_reg(pg[2], pg[3], bb + GU_GH, bb + GU_GL, brow_ld, bc0 + 2);
        cvt_store8_reg(pu[0], pu[1], bb + GU_UH, bb + GU_UL, brow_ld, bc0);
        cvt_store8_reg(pu[2], pu[3], bb + GU_UH, bb + GU_UL, brow_ld, bc0 + 2);
    };

    // warp mapping: 4(m) x 2(n)
    const int mw = (wid & 3) * 32, nw = (wid >> 2) * 32;
    const int arow = mw + (lane & 15);
    const int acs  = lane >> 4;
    const int brow = nw + (lane & 7) + ((lane & 16) ? 8 : 0);
    const int bcs  = (lane >> 3) & 1;

    float accg[2][4][4] = {}, accu[2][4][4] = {};
    float4 pg[4], pu[4];

    // prologue: stage 0 fully, synchronously
    issueA(0, 0);
    loadB(0, pg, pu);
    storeB(0, pg, pu);
    CP_ASYNC_WAIT_ALL();
    __syncthreads();

    for (int s = 0; s < NS; s++) {
        const int b = s & 1;
        if (s + 1 < NS) { issueA(s + 1, b ^ 1); loadB(s + 1, pg, pu); }
        const uint32_t base = sb + b * GU_STAGE;
        #pragma unroll
        for (int k = 0; k < 4; k++) {
            uint32_t ah[2][4], al[2][4];
            #pragma unroll
            for (int mt = 0; mt < 2; mt++) {
                uint32_t off = SMEM_SWIZZLE_128B((uint32_t)((arow + mt*16) * 128 + (2*k + acs) * 16));
                LDSM_X4(ah[mt][0], ah[mt][1], ah[mt][2], ah[mt][3], base + GU_AH + off);
                LDSM_X4(al[mt][0], al[mt][1], al[mt][2], al[mt][3], base + GU_AL + off);
            }
            uint32_t bo0 = SMEM_SWIZZLE_128B((uint32_t)(brow        * 128 + (2*k + bcs) * 16));
            uint32_t bo1 = SMEM_SWIZZLE_128B((uint32_t)((brow + 16) * 128 + (2*k + bcs) * 16));
            uint32_t gbh[8], gbl[8], ubh[8], ubl[8];
            LDSM_X4(gbh[0], gbh[1], gbh[2], gbh[3], base + GU_GH + bo0);
            LDSM_X4(gbh[4], gbh[5], gbh[6], gbh[7], base + GU_GH + bo1);
            LDSM_X4(gbl[0], gbl[1], gbl[2], gbl[3], base + GU_GL + bo0);
            LDSM_X4(gbl[4], gbl[5], gbl[6], gbl[7], base + GU_GL + bo1);
            LDSM_X4(ubh[0], ubh[1], ubh[2], ubh[3], base + GU_UH + bo0);
            LDSM_X4(ubh[4], ubh[5], ubh[6], ubh[7], base + GU_UH + bo1);
            LDSM_X4(ubl[0], ubl[1], ubl[2], ubl[3], base + GU_UL + bo0);
            LDSM_X4(ubl[4], ubl[5], ubl[6], ubl[7], base + GU_UL + bo1);
            #pragma unroll
            for (int mt = 0; mt < 2; mt++) {
                #pragma unroll
                for (int nt = 0; nt < 4; nt++) {
                    MMA16816(accg[mt][nt], ah[mt], gbh[2*nt], gbh[2*nt+1]);
                    MMA16816(accg[mt][nt], ah[mt], gbl[2*nt], gbl[2*nt+1]);
                    MMA16816(accg[mt][nt], al[mt], gbh[2*nt], gbh[2*nt+1]);
                    MMA16816(accu[mt][nt], ah[mt], ubh[2*nt], ubh[2*nt+1]);
                    MMA16816(accu[mt][nt], ah[mt], ubl[2*nt], ubl[2*nt+1]);
                    MMA16816(accu[mt][nt], al[mt], ubh[2*nt], ubh[2*nt+1]);
                }
            }
        }
        if (s + 1 < NS) storeB(b ^ 1, pg, pu);
        CP_ASYNC_WAIT_ALL();
        __syncthreads();
    }

    // SwiGLU epilogue -> bf16 hi/lo
    const int g = lane >> 2, tig = lane & 3;
    #pragma unroll
    for (int mt = 0; mt < 2; mt++) {
        #pragma unroll
        for (int nt = 0; nt < 4; nt++) {
            int r1 = m0 + mw + mt*16 + g;
            int col = n0 + nw + nt*8 + 2*tig;
            {
                float gv0 = accg[mt][nt][0], gv1 = accg[mt][nt][1];
                float h0 = accu[mt][nt][0] * gv0 / (1.f + expf(-gv0));
                float h1 = accu[mt][nt][1] * gv1 / (1.f + expf(-gv1));
                uint32_t lo, hi = pack2(h0, h1, lo);
                *(uint32_t*)(Chi + (size_t)r1 * CLD + col) = hi;
                *(uint32_t*)(Clo + (size_t)r1 * CLD + col) = lo;
            }
            {
                float gv0 = accg[mt][nt][2], gv1 = accg[mt][nt][3];
                float h0 = accu[mt][nt][2] * gv0 / (1.f + expf(-gv0));
                float h1 = accu[mt][nt][3] * gv1 / (1.f + expf(-gv1));
                uint32_t lo, hi = pack2(h0, h1, lo);
                *(uint32_t*)(Chi + (size_t)(r1 + 8) * CLD + col) = hi;
                *(uint32_t*)(Clo + (size_t)(r1 + 8) * CLD + col) = lo;
            }
        }
    }
}

// ============ down GEMM (mma.sync bf16 3-pass), A bf16 hi/lo, B fp32 reg-prefetched ============
// CTA 128x128, warp tile 64x32.
template<int ROUTED>
__global__ void __launch_bounds__(256)
dn_k(const __nv_bfloat16* __restrict__ Ah0, const __nv_bfloat16* __restrict__ Al0,
     const float* __restrict__ Bw0, float* __restrict__ C)
{
    constexpr int K  = ROUTED ? IM : ISH;
    constexpr int NS = K / BK;              // 22 or 44
    extern __shared__ char smem[];
    const uint32_t sb = smem_to_u32(smem);
    const int tid = threadIdx.x, wid = tid >> 5, lane = tid & 31;
    const int m0 = blockIdx.x * BM, n0 = blockIdx.y * 128;

    const float* bw = Bw0;
    if (ROUTED) {
        int e = d_tile_e[blockIdx.x];
        if (e < 0) return;
        bw += (size_t)e * HD * IM;
    }

    const int rb  = tid >> 3;
    const int chB = (tid & 7) * 16;
    const int chE = (tid & 7) * 8;
    uint32_t aswz[4];
    const __nv_bfloat16 *aah[4], *aal[4];
    #pragma unroll
    for (int i = 0; i < 4; i++) {
        int r = rb + i * 32;
        aswz[i] = SMEM_SWIZZLE_128B((uint32_t)(r * 128 + chB));
        aah[i] = Ah0 + (size_t)(m0 + r) * K + chE;
        aal[i] = Al0 + (size_t)(m0 + r) * K + chE;
    }
    // B-side: 128 rows, 2 threads/row, 32 consecutive fp32 each
    const int brow_ld = tid >> 1;           // 0..127
    const int bc0     = (tid & 1) * 8;      // 0 or 8
    const float* bsrc = bw + (size_t)(n0 + brow_ld) * K + bc0 * 4;

    auto issueA = [&](int s, int buf) {
        const uint32_t bs = sb + (uint32_t)buf * DN_STAGE;
        #pragma unroll
        for (int i = 0; i < 4; i++) {
            CP_ASYNC16(bs + DN_AH + aswz[i], aah[i] + s * BK);
            CP_ASYNC16(bs + DN_AL + aswz[i], aal[i] + s * BK);
        }
    };
    auto loadB = [&](int s, float4* pb) {
        const float4* b4 = (const float4*)(bsrc + s * BK);
        #pragma unroll
        for (int j = 0; j < 8; j++) pb[j] = __ldg(b4 + j);
    };
    auto storeB = [&](int buf, const float4* pb) {
        char* bb = smem + (size_t)buf * DN_STAGE;
        #pragma unroll
        for (int j = 0; j < 4; j++)
            cvt_store8_reg(pb[2*j], pb[2*j+1], bb + DN_BH, bb + DN_BL, brow_ld, bc0 + 2*j);
    };

    // warp mapping: 2(m) x 4(n)
    const int mw = (wid & 1) * 64, nw = (wid >> 1) * 32;
    const int arow = mw + (lane & 15);
    const int acs  = lane >> 4;
    const int brow = nw + (lane & 7) + ((lane & 16) ? 8 : 0);
    const int bcs  = (lane >> 3) & 1;

    float acc[4][4][4] = {};
    float4 pb[8];

    issueA(0, 0);
    loadB(0, pb);
    storeB(0, pb);
    CP_ASYNC_WAIT_ALL();
    __syncthreads();

    for (int s = 0; s < NS; s++) {
        const int b = s & 1;
        if (s + 1 < NS) { issueA(s + 1, b ^ 1); loadB(s + 1, pb); }
        const uint32_t base = sb + b * DN_STAGE;
        #pragma unroll
        for (int k = 0; k < 4; k++) {
            uint32_t ah[4][4], al[4][4];
            #pragma unroll
            for (int mt = 0; mt < 4; mt++) {
                uint32_t off = SMEM_SWIZZLE_128B((uint32_t)((arow + mt*16) * 128 + (2*k + acs) * 16));
                LDSM_X4(ah[mt][0], ah[mt][1], ah[mt][2], ah[mt][3], base + DN_AH + off);
                LDSM_X4(al[mt][0], al[mt][1], al[mt][2], al[mt][3], base + DN_AL + off);
            }
            uint32_t bo0 = SMEM_SWIZZLE_128B((uint32_t)(brow        * 128 + (2*k + bcs) * 16));
            uint32_t bo1 = SMEM_SWIZZLE_128B((uint32_t)((brow + 16) * 128 + (2*k + bcs) * 16));
            uint32_t bbh[8], bbl[8];
            LDSM_X4(bbh[0], bbh[1], bbh[2], bbh[3], base + DN_BH + bo0);
            LDSM_X4(bbh[4], bbh[5], bbh[6], bbh[7], base + DN_BH + bo1);
            LDSM_X4(bbl[0], bbl[1], bbl[2], bbl[3], base + DN_BL + bo0);
            LDSM_X4(bbl[4], bbl[5], bbl[6], bbl[7], base + DN_BL + bo1);
            #pragma unroll
            for (int mt = 0; mt < 4; mt++) {
                #pragma unroll
                for (int nt = 0; nt < 4; nt++) {
                    MMA16816(acc[mt][nt], ah[mt], bbh[2*nt], bbh[2*nt+1]);
                    MMA16816(acc[mt][nt], ah[mt], bbl[2*nt], bbl[2*nt+1]);
                    MMA16816(acc[mt][nt], al[mt], bbh[2*nt], bbh[2*nt+1]);
                }
            }
        }
        if (s + 1 < NS) storeB(b ^ 1, pb);
        CP_ASYNC_WAIT_ALL();
        __syncthreads();
    }

    const int g = lane >> 2, tig = lane & 3;
    #pragma unroll
    for (int mt = 0; mt < 4; mt++) {
        #pragma unroll
        for (int nt = 0; nt < 4; nt++) {
            int r1 = m0 + mw + mt*16 + g;
            int col = n0 + nw + nt*8 + 2*tig;
            *(float2*)(C + (size_t)r1 * HD + col)       = make_float2(acc[mt][nt][0], acc[mt][nt][1]);
            *(float2*)(C + (size_t)(r1 + 8) * HD + col) = make_float2(acc[mt][nt][2], acc[mt][nt][3]);
        }
    }
}

// ---------------- combine: out += w0*yp[p0] + w1*yp[p1] ----------------
__global__ void combine_k(float* __restrict__ out)
{
    size_t n = (size_t)T * HD;
    size_t stride = (size_t)gridDim.x * blockDim.x;
    for (size_t i = (size_t)blockIdx.x * blockDim.x + threadIdx.x; i < n; i += stride) {
        int t   = (int)(i >> 11);
        int col = (int)(i & 2047);
        int   p0 = d_pslot[2*t],  p1 = d_pslot[2*t+1];
        float w0 = d_topk_w[2*t], w1 = d_topk_w[2*t+1];
        out[i] += w0 * d_yp[(size_t)p0*HD + col] + w1 * d_yp[(size_t)p1*HD + col];
    }
}

// ---------------- launch ----------------
extern "C" void kernel_launch(void* const* d_in, const int* in_sizes, int n_in,
                              void* d_out, int out_size)
{
    const float* x    = (const float*)d_in[0];
    const float* rw   = (const float*)d_in[1];
    const float* bias = (const float*)d_in[2];
    const float* gw   = (const float*)d_in[3];
    const float* uw   = (const float*)d_in[4];
    const float* dw   = (const float*)d_in[5];
    const float* sgw  = (const float*)d_in[6];
    const float* suw  = (const float*)d_in[7];
    const float* sdw  = (const float*)d_in[8];
    float* out = (float*)d_out;

    __nv_bfloat16 *xh, *xl, *hh, *hl, *shh, *shl;
    float* yp;
    cudaGetSymbolAddress((void**)&xh,  x_hi);   cudaGetSymbolAddress((void**)&xl,  x_lo);
    cudaGetSymbolAddress((void**)&hh,  h_hi);   cudaGetSymbolAddress((void**)&hl,  h_lo);
    cudaGetSymbolAddress((void**)&shh, sh_hi);  cudaGetSymbolAddress((void**)&shl, sh_lo);
    cudaGetSymbolAddress((void**)&yp,  d_yp);

    cudaFuncSetAttribute(gu_k<1>, cudaFuncAttributeMaxDynamicSharedMemorySize, SMEM_BYTES);
    cudaFuncSetAttribute(gu_k<0>, cudaFuncAttributeMaxDynamicSharedMemorySize, SMEM_BYTES);
    cudaFuncSetAttribute(dn_k<1>, cudaFuncAttributeMaxDynamicSharedMemorySize, SMEM_BYTES);
    cudaFuncSetAttribute(dn_k<0>, cudaFuncAttributeMaxDynamicSharedMemorySize, SMEM_BYTES);

    split_k<<<512, 256>>>(x, xh, xl, (size_t)T*HD/4);
    router_k<<<T, 256>>>(x, rw, bias);
    build_pairs_k<<<1, 256>>>();

    // routed experts
    gu_k<1><<<dim3(NTILES, IM/64),  256, SMEM_BYTES>>>(xh, xl, gw, uw, hh, hl);
    dn_k<1><<<dim3(NTILES, HD/128), 256, SMEM_BYTES>>>(hh, hl, dw, yp);

    // shared expert
    gu_k<0><<<dim3(T/BM, ISH/64),  256, SMEM_BYTES>>>(xh, xl, sgw, suw, shh, shl);
    dn_k<0><<<dim3(T/BM, HD/128),  256, SMEM_BYTES>>>(shh, shl, sdw, out);

    combine_k<<<2048, 256>>>(out);
}

// round 10
// speedup vs baseline: 2.7248x; 1.0023x over previous
#include <cuda_runtime.h>
#include <cuda_bf16.h>
#include <cstdint>
#include <math.h>

// ---------------- problem constants ----------------
#define T     2048
#define HD    2048          // hidden
#define E     8             // routed experts
#define IM    1408          // moe intermediate
#define ISH   2816          // shared intermediate
#define BM    128
#define BK    64            // bf16 k elems per stage (=128B rows)
#define MAXP  (2*T + E*BM)  // 5120 padded pair rows
#define NTILES (MAXP/BM)    // 40

// gu stage smem layout (bytes)
#define GU_AH 0
#define GU_AL 16384
#define GU_GH 32768
#define GU_GL 40960
#define GU_UH 49152
#define GU_UL 57344
#define GU_STAGE 65536
// down stage layout
#define DN_AH 0
#define DN_AL 16384
#define DN_BH 32768
#define DN_BL 49152
#define DN_STAGE 65536
#define SMEM_BYTES (2*GU_STAGE)   // 131072 for both kernels

#define SMEM_SWIZZLE_128B(off) ((off) ^ (((off) >> 3) & 0x70))

__device__ __forceinline__ uint32_t smem_to_u32(const void* p) {
    uint32_t a;
    asm("{ .reg .u64 t; cvta.to.shared.u64 t, %1; cvt.u32.u64 %0, t; }" : "=r"(a) : "l"(p));
    return a;
}

#define CP_ASYNC16(dst_u32, src_ptr) \
    asm volatile("cp.async.cg.shared.global [%0], [%1], 16;" :: "r"(dst_u32), "l"(src_ptr))
#define CP_ASYNC_WAIT_ALL() asm volatile("cp.async.wait_all;" ::: "memory")

#define LDSM_X4(d0,d1,d2,d3,a) \
    asm volatile("ldmatrix.sync.aligned.m8n8.x4.shared.b16 {%0,%1,%2,%3}, [%4];" \
        : "=r"(d0), "=r"(d1), "=r"(d2), "=r"(d3) : "r"(a))

#define MMA16816(d, a, b0, b1) \
    asm volatile("mma.sync.aligned.m16n8k16.row.col.f32.bf16.bf16.f32 " \
        "{%0,%1,%2,%3}, {%4,%5,%6,%7}, {%8,%9}, {%0,%1,%2,%3};" \
        : "+f"((d)[0]), "+f"((d)[1]), "+f"((d)[2]), "+f"((d)[3]) \
        : "r"((a)[0]), "r"((a)[1]), "r"((a)[2]), "r"((a)[3]), "r"(b0), "r"(b1))

// fp32 -> bf16 hi/lo split of two consecutive values, packed bf16x2
__device__ __forceinline__ uint32_t pack2(float x, float y, uint32_t& lob) {
    __nv_bfloat162 h = __float22bfloat162_rn(make_float2(x, y));
    float2 hf = __bfloat1622float2(h);
    __nv_bfloat162 l = __float22bfloat162_rn(make_float2(x - hf.x, y - hf.y));
    lob = *reinterpret_cast<uint32_t*>(&l);
    return *reinterpret_cast<uint32_t*>(&h);
}

// convert two prefetched float4 (8 fp32) -> swizzled bf16 hi/lo 16B stores
__device__ __forceinline__ void cvt_store8_reg(float4 a, float4 b, char* hibase, char* lobase,
                                               int row, int c2)
{
    uint32_t l0, l1, l2, l3;
    uint32_t h0 = pack2(a.x, a.y, l0);
    uint32_t h1 = pack2(a.z, a.w, l1);
    uint32_t h2 = pack2(b.x, b.y, l2);
    uint32_t h3 = pack2(b.z, b.w, l3);
    uint32_t sw = SMEM_SWIZZLE_128B((uint32_t)(row * 128 + c2 * 8));
    *(uint4*)(hibase + sw) = make_uint4(h0, h1, h2, h3);
    *(uint4*)(lobase + sw) = make_uint4(l0, l1, l2, l3);
}

// ---------------- device scratch (static) ----------------
__device__ int   d_topk_idx[2*T];
__device__ float d_topk_w[2*T];
__device__ int   d_cnt[E];
__device__ int   d_off[E];
__device__ int   d_tile_e[NTILES];
__device__ int   d_ptok[MAXP];
__device__ int   d_pslot[2*T];
__device__ __nv_bfloat16 x_hi[(size_t)T*HD],    x_lo[(size_t)T*HD];
__device__ __nv_bfloat16 h_hi[(size_t)MAXP*IM], h_lo[(size_t)MAXP*IM];
__device__ __nv_bfloat16 sh_hi[(size_t)T*ISH],  sh_lo[(size_t)T*ISH];
__device__ float d_yp[(size_t)MAXP*HD];

// ---------------- split: fp32 -> bf16 hi + lo (x only) ----------------
__global__ void split_k(const float* __restrict__ s,
                        __nv_bfloat16* __restrict__ hi, __nv_bfloat16* __restrict__ lo,
                        size_t n4)
{
    size_t stride = (size_t)gridDim.x * blockDim.x;
    const float4* s4 = (const float4*)s;
    uint2* h2 = (uint2*)hi;
    uint2* l2 = (uint2*)lo;
    for (size_t i = (size_t)blockIdx.x * blockDim.x + threadIdx.x; i < n4; i += stride) {
        float4 v = s4[i];
        uint32_t l0, l1;
        uint32_t h0 = pack2(v.x, v.y, l0);
        uint32_t h1 = pack2(v.z, v.w, l1);
        h2[i] = make_uint2(h0, h1);
        l2[i] = make_uint2(l0, l1);
    }
}

// ---------------- router ----------------
__global__ void router_k(const float* __restrict__ x,
                         const float* __restrict__ rw,
                         const float* __restrict__ bias)
{
    __shared__ float xs[HD];
    __shared__ float logits[E];
    int t = blockIdx.x, tid = threadIdx.x;
    for (int i = tid; i < HD; i += blockDim.x) xs[i] = x[(size_t)t*HD + i];
    __syncthreads();
    int wid = tid >> 5, lane = tid & 31;
    if (wid < E) {
        float s = 0.f;
        for (int k = lane; k < HD; k += 32) s += xs[k] * rw[wid*HD + k];
        #pragma unroll
        for (int o = 16; o; o >>= 1) s += __shfl_down_sync(0xffffffffu, s, o);
        if (!lane) logits[wid] = s;
    }
    __syncthreads();
    if (tid == 0) {
        float sc[E], sfc[E];
        #pragma unroll
        for (int e = 0; e < E; e++) {
            sc[e]  = 1.f / (1.f + expf(-logits[e]));
            sfc[e] = sc[e] + bias[e];
        }
        float gs[4];
        #pragma unroll
        for (int g = 0; g < 4; g++) gs[g] = sfc[2*g] + sfc[2*g+1];
        int g1 = 0;
        #pragma unroll
        for (int g = 1; g < 4; g++) if (gs[g] > gs[g1]) g1 = g;
        int g2 = -1;
        #pragma unroll
        for (int g = 0; g < 4; g++) { if (g == g1) continue; if (g2 < 0 || gs[g] > gs[g2]) g2 = g; }
        float masked[E];
        #pragma unroll
        for (int e = 0; e < E; e++) { int g = e >> 1; masked[e] = (g == g1 || g == g2) ? sfc[e] : 0.f; }
        int i1 = 0;
        #pragma unroll
        for (int e = 1; e < E; e++) if (masked[e] > masked[i1]) i1 = e;
        int i2 = -1;
        #pragma unroll
        for (int e = 0; e < E; e++) { if (e == i1) continue; if (i2 < 0 || masked[e] > masked[i2]) i2 = e; }
        float w1 = sc[i1], w2 = sc[i2];
        float inv = 2.5f / (w1 + w2 + 1e-20f);
        d_topk_idx[2*t] = i1; d_topk_idx[2*t+1] = i2;
        d_topk_w[2*t]   = w1 * inv;
        d_topk_w[2*t+1] = w2 * inv;
    }
}

// ---------------- deterministic pair list ----------------
__global__ void build_pairs_k()
{
    __shared__ int cnts[E], offs[E];
    int tid = threadIdx.x, wid = tid >> 5, lane = tid & 31;
    for (int i = tid; i < MAXP; i += blockDim.x) d_ptok[i] = 0;  // padded rows -> token 0
    if (wid < E) {
        int c = 0;
        for (int base = 0; base < T; base += 32) {
            int t = base + lane;
            bool sel = (d_topk_idx[2*t] == wid) || (d_topk_idx[2*t+1] == wid);
            c += __popc(__ballot_sync(0xffffffffu, sel));
        }
        if (!lane) cnts[wid] = c;
    }
    __syncthreads();
    if (tid == 0) {
        int o = 0;
        for (int e = 0; e < E; e++) {
            offs[e] = o; d_off[e] = o; d_cnt[e] = cnts[e];
            o += ((cnts[e] + BM - 1) / BM) * BM;
        }
        int tcur = 0;
        for (int e = 0; e < E; e++) {
            int t0 = offs[e] / BM, nt = (cnts[e] + BM - 1) / BM;
            for (int i = 0; i < nt; i++) d_tile_e[t0 + i] = e;
            tcur = t0 + nt;
        }
        for (int i = tcur; i < NTILES; i++) d_tile_e[i] = -1;
    }
    __syncthreads();
    if (wid < E) {
        int pos = offs[wid];
        for (int base = 0; base < T; base += 32) {
            int t = base + lane;
            int e0 = d_topk_idx[2*t], e1 = d_topk_idx[2*t+1];
            int j = (e0 == wid) ? 0 : ((e1 == wid) ? 1 : -1);
            unsigned m = __ballot_sync(0xffffffffu, j >= 0);
            if (j >= 0) {
                int p = pos + __popc(m & ((1u << lane) - 1u));
                d_ptok[p] = t;
                d_pslot[2*t+j] = p;
            }
            pos += __popc(m);
        }
    }
}

// ============ fused gate+up GEMM (mma.sync bf16 3-pass) + SwiGLU epilogue ============
// CTA 128x64, K = HD. Weight LDGs register-prefetched; MMA passes reordered so
// consecutive MMAs never share an accumulator (dependency-stall fix).
template<int ROUTED>
__global__ void __launch_bounds__(256)
gu_k(const __nv_bfloat16* __restrict__ Xh, const __nv_bfloat16* __restrict__ Xl,
     const float* __restrict__ Gw0, const float* __restrict__ Uw0,
     __nv_bfloat16* __restrict__ Chi, __nv_bfloat16* __restrict__ Clo)
{
    constexpr int NS  = HD / BK;            // 32
    constexpr int CLD = ROUTED ? IM : ISH;
    extern __shared__ char smem[];
    const uint32_t sb = smem_to_u32(smem);
    const int tid = threadIdx.x, wid = tid >> 5, lane = tid & 31;
    const int m0 = blockIdx.x * BM, n0 = blockIdx.y * 64;

    const float *gw = Gw0, *uw = Uw0;
    if (ROUTED) {
        int e = d_tile_e[blockIdx.x];
        if (e < 0) return;
        size_t eo = (size_t)e * IM * HD;
        gw += eo; uw += eo;
    }

    // A-plane cp.async descriptors
    const int rb  = tid >> 3;               // 0..31
    const int chB = (tid & 7) * 16;
    const int chE = (tid & 7) * 8;
    const __nv_bfloat16 *axh[4], *axl[4];
    uint32_t aswz[4];
    #pragma unroll
    for (int i = 0; i < 4; i++) {
        int r = rb + i * 32;
        int gr = m0 + r;
        int srow = ROUTED ? d_ptok[gr] : gr;
        aswz[i] = SMEM_SWIZZLE_128B((uint32_t)(r * 128 + chB));
        axh[i] = Xh + (size_t)srow * HD + chE;
        axl[i] = Xl + (size_t)srow * HD + chE;
    }
    // B-side (fp32 weights): 64 rows, 4 threads/row, 16 consecutive fp32 each
    const int brow_ld = tid >> 2;           // 0..63
    const int bc0     = (tid & 3) * 4;      // chunk base: 0,4,8,12 (fp32 elems = bc0*4)
    const float* gsrc = gw + (size_t)(n0 + brow_ld) * HD + bc0 * 4;
    const float* usrc = uw + (size_t)(n0 + brow_ld) * HD + bc0 * 4;

    auto issueA = [&](int s, int buf) {
        const uint32_t bs = sb + (uint32_t)buf * GU_STAGE;
        #pragma unroll
        for (int i = 0; i < 4; i++) {
            CP_ASYNC16(bs + GU_AH + aswz[i], axh[i] + s * BK);
            CP_ASYNC16(bs + GU_AL + aswz[i], axl[i] + s * BK);
        }
    };
    auto loadB = [&](int s, float4* pg, float4* pu) {
        const float4* g4 = (const float4*)(gsrc + s * BK);
        const float4* u4 = (const float4*)(usrc + s * BK);
        #pragma unroll
        for (int j = 0; j < 4; j++) { pg[j] = __ldg(g4 + j); pu[j] = __ldg(u4 + j); }
    };
    auto storeB = [&](int buf, const float4* pg, const float4* pu) {
        char* bb = smem + (size_t)buf * GU_STAGE;
        cvt_store8_reg(pg[0], pg[1], bb + GU_GH, bb + GU_GL, brow_ld, bc0);
        cvt_store8_reg(pg[2], pg[3], bb + GU_GH, bb + GU_GL, brow_ld, bc0 + 2);
        cvt_store8_reg(pu[0], pu[1], bb + GU_UH, bb + GU_UL, brow_ld, bc0);
        cvt_store8_reg(pu[2], pu[3], bb + GU_UH, bb + GU_UL, brow_ld, bc0 + 2);
    };

    // warp mapping: 4(m) x 2(n)
    const int mw = (wid & 3) * 32, nw = (wid >> 2) * 32;
    const int arow = mw + (lane & 15);
    const int acs  = lane >> 4;
    const int brow = nw + (lane & 7) + ((lane & 16) ? 8 : 0);
    const int bcs  = (lane >> 3) & 1;

    float accg[2][4][4] = {}, accu[2][4][4] = {};
    float4 pg[4], pu[4];

    // prologue: stage 0 fully, synchronously
    issueA(0, 0);
    loadB(0, pg, pu);
    storeB(0, pg, pu);
    CP_ASYNC_WAIT_ALL();
    __syncthreads();

    for (int s = 0; s < NS; s++) {
        const int b = s & 1;
        if (s + 1 < NS) { issueA(s + 1, b ^ 1); loadB(s + 1, pg, pu); }
        const uint32_t base = sb + b * GU_STAGE;
        #pragma unroll
        for (int k = 0; k < 4; k++) {
            uint32_t ah[2][4], al[2][4];
            #pragma unroll
            for (int mt = 0; mt < 2; mt++) {
                uint32_t off = SMEM_SWIZZLE_128B((uint32_t)((arow + mt*16) * 128 + (2*k + acs) * 16));
                LDSM_X4(ah[mt][0], ah[mt][1], ah[mt][2], ah[mt][3], base + GU_AH + off);
                LDSM_X4(al[mt][0], al[mt][1], al[mt][2], al[mt][3], base + GU_AL + off);
            }
            uint32_t bo0 = SMEM_SWIZZLE_128B((uint32_t)(brow        * 128 + (2*k + bcs) * 16));
            uint32_t bo1 = SMEM_SWIZZLE_128B((uint32_t)((brow + 16) * 128 + (2*k + bcs) * 16));
            uint32_t gbh[8], gbl[8], ubh[8], ubl[8];
            LDSM_X4(gbh[0], gbh[1], gbh[2], gbh[3], base + GU_GH + bo0);
            LDSM_X4(gbh[4], gbh[5], gbh[6], gbh[7], base + GU_GH + bo1);
            LDSM_X4(gbl[0], gbl[1], gbl[2], gbl[3], base + GU_GL + bo0);
            LDSM_X4(gbl[4], gbl[5], gbl[6], gbl[7], base + GU_GL + bo1);
            LDSM_X4(ubh[0], ubh[1], ubh[2], ubh[3], base + GU_UH + bo0);
            LDSM_X4(ubh[4], ubh[5], ubh[6], ubh[7], base + GU_UH + bo1);
            LDSM_X4(ubl[0], ubl[1], ubl[2], ubl[3], base + GU_UL + bo0);
            LDSM_X4(ubl[4], ubl[5], ubl[6], ubl[7], base + GU_UL + bo1);
            // pass-major issue order: 8 independent MMAs between same-acc reuses.
            // Per-accumulator term order unchanged (Ah*Bh, Ah*Bl, Al*Bh) -> bitwise-identical.
            #pragma unroll
            for (int mt = 0; mt < 2; mt++)
                #pragma unroll
                for (int nt = 0; nt < 4; nt++)
                    MMA16816(accg[mt][nt], ah[mt], gbh[2*nt], gbh[2*nt+1]);
            #pragma unroll
            for (int mt = 0; mt < 2; mt++)
                #pragma unroll
                for (int nt = 0; nt < 4; nt++)
                    MMA16816(accu[mt][nt], ah[mt], ubh[2*nt], ubh[2*nt+1]);
            #pragma unroll
            for (int mt = 0; mt < 2; mt++)
                #pragma unroll
                for (int nt = 0; nt < 4; nt++)
                    MMA16816(accg[mt][nt], ah[mt], gbl[2*nt], gbl[2*nt+1]);
            #pragma unroll
            for (int mt = 0; mt < 2; mt++)
                #pragma unroll
                for (int nt = 0; nt < 4; nt++)
                    MMA16816(accu[mt][nt], ah[mt], ubl[2*nt], ubl[2*nt+1]);
            #pragma unroll
            for (int mt = 0; mt < 2; mt++)
                #pragma unroll
                for (int nt = 0; nt < 4; nt++)
                    MMA16816(accg[mt][nt], al[mt], gbh[2*nt], gbh[2*nt+1]);
            #pragma unroll
            for (int mt = 0; mt < 2; mt++)
                #pragma unroll
                for (int nt = 0; nt < 4; nt++)
                    MMA16816(accu[mt][nt], al[mt], ubh[2*nt], ubh[2*nt+1]);
        }
        if (s + 1 < NS) storeB(b ^ 1, pg, pu);
        CP_ASYNC_WAIT_ALL();
        __syncthreads();
    }

    // SwiGLU epilogue -> bf16 hi/lo
    const int g = lane >> 2, tig = lane & 3;
    #pragma unroll
    for (int mt = 0; mt < 2; mt++) {
        #pragma unroll
        for (int nt = 0; nt < 4; nt++) {
            int r1 = m0 + mw + mt*16 + g;
            int col = n0 + nw + nt*8 + 2*tig;
            {
                float gv0 = accg[mt][nt][0], gv1 = accg[mt][nt][1];
                float h0 = accu[mt][nt][0] * gv0 / (1.f + expf(-gv0));
                float h1 = accu[mt][nt][1] * gv1 / (1.f + expf(-gv1));
                uint32_t lo, hi = pack2(h0, h1, lo);
                *(uint32_t*)(Chi + (size_t)r1 * CLD + col) = hi;
                *(uint32_t*)(Clo + (size_t)r1 * CLD + col) = lo;
            }
            {
                float gv0 = accg[mt][nt][2], gv1 = accg[mt][nt][3];
                float h0 = accu[mt][nt][2] * gv0 / (1.f + expf(-gv0));
                float h1 = accu[mt][nt][3] * gv1 / (1.f + expf(-gv1));
                uint32_t lo, hi = pack2(h0, h1, lo);
                *(uint32_t*)(Chi + (size_t)(r1 + 8) * CLD + col) = hi;
                *(uint32_t*)(Clo + (size_t)(r1 + 8) * CLD + col) = lo;
            }
        }
    }
}

// ============ down GEMM (mma.sync bf16 3-pass), A bf16 hi/lo, B fp32 reg-prefetched ============
// CTA 128x128, warp tile 64x32. Pass-major MMA order (16 independent between reuses).
template<int ROUTED>
__global__ void __launch_bounds__(256)
dn_k(const __nv_bfloat16* __restrict__ Ah0, const __nv_bfloat16* __restrict__ Al0,
     const float* __restrict__ Bw0, float* __restrict__ C)
{
    constexpr int K  = ROUTED ? IM : ISH;
    constexpr int NS = K / BK;              // 22 or 44
    extern __shared__ char smem[];
    const uint32_t sb = smem_to_u32(smem);
    const int tid = threadIdx.x, wid = tid >> 5, lane = tid & 31;
    const int m0 = blockIdx.x * BM, n0 = blockIdx.y * 128;

    const float* bw = Bw0;
    if (ROUTED) {
        int e = d_tile_e[blockIdx.x];
        if (e < 0) return;
        bw += (size_t)e * HD * IM;
    }

    const int rb  = tid >> 3;
    const int chB = (tid & 7) * 16;
    const int chE = (tid & 7) * 8;
    uint32_t aswz[4];
    const __nv_bfloat16 *aah[4], *aal[4];
    #pragma unroll
    for (int i = 0; i < 4; i++) {
        int r = rb + i * 32;
        aswz[i] = SMEM_SWIZZLE_128B((uint32_t)(r * 128 + chB));
        aah[i] = Ah0 + (size_t)(m0 + r) * K + chE;
        aal[i] = Al0 + (size_t)(m0 + r) * K + chE;
    }
    // B-side: 128 rows, 2 threads/row, 32 consecutive fp32 each
    const int brow_ld = tid >> 1;           // 0..127
    const int bc0     = (tid & 1) * 8;      // 0 or 8
    const float* bsrc = bw + (size_t)(n0 + brow_ld) * K + bc0 * 4;

    auto issueA = [&](int s, int buf) {
        const uint32_t bs = sb + (uint32_t)buf * DN_STAGE;
        #pragma unroll
        for (int i = 0; i < 4; i++) {
            CP_ASYNC16(bs + DN_AH + aswz[i], aah[i] + s * BK);
            CP_ASYNC16(bs + DN_AL + aswz[i], aal[i] + s * BK);
        }
    };
    auto loadB = [&](int s, float4* pb) {
        const float4* b4 = (const float4*)(bsrc + s * BK);
        #pragma unroll
        for (int j = 0; j < 8; j++) pb[j] = __ldg(b4 + j);
    };
    auto storeB = [&](int buf, const float4* pb) {
        char* bb = smem + (size_t)buf * DN_STAGE;
        #pragma unroll
        for (int j = 0; j < 4; j++)
            cvt_store8_reg(pb[2*j], pb[2*j+1], bb + DN_BH, bb + DN_BL, brow_ld, bc0 + 2*j);
    };

    // warp mapping: 2(m) x 4(n)
    const int mw = (wid & 1) * 64, nw = (wid >> 1) * 32;
    const int arow = mw + (lane & 15);
    const int acs  = lane >> 4;
    const int brow = nw + (lane & 7) + ((lane & 16) ? 8 : 0);
    const int bcs  = (lane >> 3) & 1;

    float acc[4][4][4] = {};
    float4 pb[8];

    issueA(0, 0);
    loadB(0, pb);
    storeB(0, pb);
    CP_ASYNC_WAIT_ALL();
    __syncthreads();

    for (int s = 0; s < NS; s++) {
        const int b = s & 1;
        if (s + 1 < NS) { issueA(s + 1, b ^ 1); loadB(s + 1, pb); }
        const uint32_t base = sb + b * DN_STAGE;
        #pragma unroll
        for (int k = 0; k < 4; k++) {
            uint32_t ah[4][4], al[4][4];
            #pragma unroll
            for (int mt = 0; mt < 4; mt++) {
                uint32_t off = SMEM_SWIZZLE_128B((uint32_t)((arow + mt*16) * 128 + (2*k + acs) * 16));
                LDSM_X4(ah[mt][0], ah[mt][1], ah[mt][2], ah[mt][3], base + DN_AH + off);
                LDSM_X4(al[mt][0], al[mt][1], al[mt][2], al[mt][3], base + DN_AL + off);
            }
            uint32_t bo0 = SMEM_SWIZZLE_128B((uint32_t)(brow        * 128 + (2*k + bcs) * 16));
            uint32_t bo1 = SMEM_SWIZZLE_128B((uint32_t)((brow + 16) * 128 + (2*k + bcs) * 16));
            uint32_t bbh[8], bbl[8];
            LDSM_X4(bbh[0], bbh[1], bbh[2], bbh[3], base + DN_BH + bo0);
            LDSM_X4(bbh[4], bbh[5], bbh[6], bbh[7], base + DN_BH + bo1);
            LDSM_X4(bbl[0], bbl[1], bbl[2], bbl[3], base + DN_BL + bo0);
            LDSM_X4(bbl[4], bbl[5], bbl[6], bbl[7], base + DN_BL + bo1);
            // pass-major: 16 independent MMAs between same-acc reuses
            #pragma unroll
            for (int mt = 0; mt < 4; mt++)
                #pragma unroll
                for (int nt = 0; nt < 4; nt++)
                    MMA16816(acc[mt][nt], ah[mt], bbh[2*nt], bbh[2*nt+1]);
            #pragma unroll
            for (int mt = 0; mt < 4; mt++)
                #pragma unroll
                for (int nt = 0; nt < 4; nt++)
                    MMA16816(acc[mt][nt], ah[mt], bbl[2*nt], bbl[2*nt+1]);
            #pragma unroll
            for (int mt = 0; mt < 4; mt++)
                #pragma unroll
                for (int nt = 0; nt < 4; nt++)
                    MMA16816(acc[mt][nt], al[mt], bbh[2*nt], bbh[2*nt+1]);
        }
        if (s + 1 < NS) storeB(b ^ 1, pb);
        CP_ASYNC_WAIT_ALL();
        __syncthreads();
    }

    const int g = lane >> 2, tig = lane & 3;
    #pragma unroll
    for (int mt = 0; mt < 4; mt++) {
        #pragma unroll
        for (int nt = 0; nt < 4; nt++) {
            int r1 = m0 + mw + mt*16 + g;
            int col = n0 + nw + nt*8 + 2*tig;
            *(float2*)(C + (size_t)r1 * HD + col)       = make_float2(acc[mt][nt][0], acc[mt][nt][1]);
            *(float2*)(C + (size_t)(r1 + 8) * HD + col) = make_float2(acc[mt][nt][2], acc[mt][nt][3]);
        }
    }
}

// ---------------- combine: out += w0*yp[p0] + w1*yp[p1] ----------------
__global__ void combine_k(float* __restrict__ out)
{
    size_t n = (size_t)T * HD;
    size_t stride = (size_t)gridDim.x * blockDim.x;
    for (size_t i = (size_t)blockIdx.x * blockDim.x + threadIdx.x; i < n; i += stride) {
        int t   = (int)(i >> 11);
        int col = (int)(i & 2047);
        int   p0 = d_pslot[2*t],  p1 = d_pslot[2*t+1];
        float w0 = d_topk_w[2*t], w1 = d_topk_w[2*t+1];
        out[i] += w0 * d_yp[(size_t)p0*HD + col] + w1 * d_yp[(size_t)p1*HD + col];
    }
}

// ---------------- launch ----------------
extern "C" void kernel_launch(void* const* d_in, const int* in_sizes, int n_in,
                              void* d_out, int out_size)
{
    const float* x    = (const float*)d_in[0];
    const float* rw   = (const float*)d_in[1];
    const float* bias = (const float*)d_in[2];
    const float* gw   = (const float*)d_in[3];
    const float* uw   = (const float*)d_in[4];
    const float* dw   = (const float*)d_in[5];
    const float* sgw  = (const float*)d_in[6];
    const float* suw  = (const float*)d_in[7];
    const float* sdw  = (const float*)d_in[8];
    float* out = (float*)d_out;

    __nv_bfloat16 *xh, *xl, *hh, *hl, *shh, *shl;
    float* yp;
    cudaGetSymbolAddress((void**)&xh,  x_hi);   cudaGetSymbolAddress((void**)&xl,  x_lo);
    cudaGetSymbolAddress((void**)&hh,  h_hi);   cudaGetSymbolAddress((void**)&hl,  h_lo);
    cudaGetSymbolAddress((void**)&shh, sh_hi);  cudaGetSymbolAddress((void**)&shl, sh_lo);
    cudaGetSymbolAddress((void**)&yp,  d_yp);

    cudaFuncSetAttribute(gu_k<1>, cudaFuncAttributeMaxDynamicSharedMemorySize, SMEM_BYTES);
    cudaFuncSetAttribute(gu_k<0>, cudaFuncAttributeMaxDynamicSharedMemorySize, SMEM_BYTES);
    cudaFuncSetAttribute(dn_k<1>, cudaFuncAttributeMaxDynamicSharedMemorySize, SMEM_BYTES);
    cudaFuncSetAttribute(dn_k<0>, cudaFuncAttributeMaxDynamicSharedMemorySize, SMEM_BYTES);

    split_k<<<512, 256>>>(x, xh, xl, (size_t)T*HD/4);
    router_k<<<T, 256>>>(x, rw, bias);
    build_pairs_k<<<1, 256>>>();

    // routed experts
    gu_k<1><<<dim3(NTILES, IM/64),  256, SMEM_BYTES>>>(xh, xl, gw, uw, hh, hl);
    dn_k<1><<<dim3(NTILES, HD/128), 256, SMEM_BYTES>>>(hh, hl, dw, yp);

    // shared expert
    gu_k<0><<<dim3(T/BM, ISH/64),  256, SMEM_BYTES>>>(xh, xl, sgw, suw, shh, shl);
    dn_k<0><<<dim3(T/BM, HD/128),  256, SMEM_BYTES>>>(shh, shl, sdw, out);

    combine_k<<<2048, 256>>>(out);
}